// round 12
// baseline (speedup 1.0000x reference)
#include <cuda_runtime.h>
#include <cuda_fp16.h>
#include <math.h>

#define NN   100000
#define EE   1600000
#define DIN  128
#define HD   64      // HEADS*HID
#define HEADS 4
#define HID  16
#define DOUT 32
#define NEG  0.2f
#define NBLK ((NN + 1023) / 1024)   // scan blocks = 98
#define KC   32                      // k-chunk
#define XS_STRIDE 36
#define G1_SMEM ((DIN * HD + 128 * XS_STRIDE) * 4)   // 51200 B
#define FULLM 0xffffffffu

typedef unsigned long long u64;

// ---------------- scratch (device globals; no allocation allowed) ----------
__device__ __align__(16) __half g_h1h[NN * HD];     // x @ W1   (fp16 storage)
__device__ __align__(16) float g_als1[NN * HEADS];
__device__ __align__(16) float g_ald1[NN * HEADS];
__device__ __align__(16) __half g_t2h[NN * DOUT];   // feat1 @ W2 (fp16 storage)
__device__ __align__(16) float g_als2[NN];
__device__ __align__(16) float g_ald2[NN];
// CSR scratch
__device__ __align__(16) int g_src[EE];
__device__ __align__(16) int g_dst[EE];
__device__ __align__(16) int g_rank[EE];            // per-dst arrival rank
__device__ int g_cnt[NN];
__device__ int g_indptr[NN + 1];
__device__ int g_indices[EE];
__device__ int g_bsum[NBLK];
__device__ int g_is64;

__global__ void gemm1_kernel(const float*, const float*, const float*, const float*);

// ---------------- stream/event for fork-join overlap (created pre-main) ----
static cudaStream_t g_s2;
static cudaEvent_t g_evFork, g_evJoin;
static struct Boot {
    Boot() {
        cudaStreamCreateWithFlags(&g_s2, cudaStreamNonBlocking);
        cudaEventCreateWithFlags(&g_evFork, cudaEventDisableTiming);
        cudaEventCreateWithFlags(&g_evJoin, cudaEventDisableTiming);
        cudaFuncSetAttribute(gemm1_kernel,
                             cudaFuncAttributeMaxDynamicSharedMemorySize, G1_SMEM);
    }
} g_boot;

__device__ __forceinline__ float lrelu_exp(float l) {
    l = fmaxf(l, NEG * l);                // branchless leaky relu
    return __expf(fminf(l, 25.f));        // clamp is a no-op safety net
}

// ---- packed fp32x2 helpers (sm_103a FFMA2 path; exact fp32 rounding) ------
__device__ __forceinline__ u64 packf2(float a, float b) {
    u64 r; asm("mov.b64 %0, {%1, %2};" : "=l"(r) : "f"(a), "f"(b)); return r;
}
__device__ __forceinline__ void ffma2(u64& d, u64 a, u64 b) {
    asm("fma.rn.f32x2 %0, %1, %2, %0;" : "+l"(d) : "l"(a), "l"(b));
}
__device__ __forceinline__ float2 unpackf2(u64 v) {
    float2 r; asm("mov.b64 {%0, %1}, %2;" : "=f"(r.x), "=f"(r.y) : "l"(v)); return r;
}

// ---------------- detect dtype (1 warp) ------------------------------------
__global__ void detect_kernel(const long long* ei) {
    if (threadIdx.x == 0) {
        int ok = 1;
        for (int k = 0; k < 64; k++) {
            long long v = ei[k];
            if (v < 0 || v >= NN) { ok = 0; break; }
        }
        g_is64 = ok;
    }
}

// ---------------- convert + count + rank (2 edges/thread) ------------------
__global__ void convert_count_kernel(const long long* __restrict__ ei) {
    int e = (blockIdx.x * blockDim.x + threadIdx.x) * 2;
    if (e >= EE) return;
    int s0, s1, d0, d1;
    if (g_is64) {
        longlong2 sv = *(const longlong2*)&ei[e];
        longlong2 dv = *(const longlong2*)&ei[e + EE];
        s0 = (int)sv.x; s1 = (int)sv.y; d0 = (int)dv.x; d1 = (int)dv.y;
    } else {
        const int* p = (const int*)ei;
        int2 sv = *(const int2*)&p[e];
        int2 dv = *(const int2*)&p[e + EE];
        s0 = sv.x; s1 = sv.y; d0 = dv.x; d1 = dv.y;
    }
    *(int2*)&g_src[e] = make_int2(s0, s1);
    *(int2*)&g_dst[e] = make_int2(d0, d1);
    int r0 = atomicAdd(&g_cnt[d0], 1);
    int r1 = atomicAdd(&g_cnt[d1], 1);
    *(int2*)&g_rank[e] = make_int2(r0, r1);
}

// ---------------- scan phase 1: per-block exclusive scan -------------------
__global__ void scan1_kernel() {
    __shared__ int wsum[32];
    int t = threadIdx.x;
    int i = blockIdx.x * 1024 + t;
    int v = (i < NN) ? g_cnt[i] : 0;
    int lane = t & 31, wid = t >> 5;
    int p = v;
    #pragma unroll
    for (int off = 1; off < 32; off <<= 1) {
        int a = __shfl_up_sync(FULLM, p, off);
        if (lane >= off) p += a;
    }
    if (lane == 31) wsum[wid] = p;
    __syncthreads();
    if (wid == 0) {
        int s = wsum[lane];
        #pragma unroll
        for (int off = 1; off < 32; off <<= 1) {
            int a = __shfl_up_sync(FULLM, s, off);
            if (lane >= off) s += a;
        }
        wsum[lane] = s;
    }
    __syncthreads();
    int base = (wid > 0) ? wsum[wid - 1] : 0;
    int incl = p + base;
    if (i < NN) g_indptr[i] = incl - v;      // exclusive within block
    if (t == 1023) g_bsum[blockIdx.x] = incl;
}

// ---------------- scan phase 2+3 merged ------------------------------------
__global__ void scan23_kernel() {
    int i = blockIdx.x * blockDim.x + threadIdx.x;
    int j = (int)((blockIdx.x * blockDim.x) >> 10);
    int lane = threadIdx.x & 31;
    int acc = 0;
    for (int k = lane; k < j; k += 32) acc += g_bsum[k];
    #pragma unroll
    for (int off = 16; off > 0; off >>= 1)
        acc += __shfl_xor_sync(FULLM, acc, off);
    if (i < NN) g_indptr[i] += acc;
    if (i == 0) g_indptr[NN] = EE;
}

// ---------------- CSR scatter: 2 edges/thread, rank precomputed ------------
__global__ void scatter_kernel() {
    int e = (blockIdx.x * blockDim.x + threadIdx.x) * 2;
    if (e >= EE) return;
    int2 s = *(const int2*)&g_src[e];
    int2 d = *(const int2*)&g_dst[e];
    int2 r = *(const int2*)&g_rank[e];
    g_indices[g_indptr[d.x] + r.x] = s.x;
    g_indices[g_indptr[d.y] + r.y] = s.y;
}

// ---------------- GEMM1 (smem W, chunked xs, packed FFMA2) + als1/ald1 -----
__global__ __launch_bounds__(256, 4)
void gemm1_kernel(const float* __restrict__ x, const float* __restrict__ W,
                  const float* __restrict__ a_src, const float* __restrict__ a_dst) {
    extern __shared__ float sm[];
    float* ws = sm;                         // [128][64]
    float* xs = sm + DIN * HD;              // [128][XS_STRIDE]
    int t = threadIdx.x;
    int bn = blockIdx.x * 128;
    for (int i = t; i < DIN * HD / 4; i += 256)
        ((float4*)ws)[i] = ((const float4*)W)[i];

    int colq = t & 7;
    int nr   = t >> 3;
    u64 accA[4][2], accB[4][2];
    #pragma unroll
    for (int i = 0; i < 4; i++) {
        accA[i][0] = accA[i][1] = 0ULL;
        accB[i][0] = accB[i][1] = 0ULL;
    }
    for (int kc = 0; kc < DIN; kc += KC) {
        __syncthreads();
        #pragma unroll
        for (int i = t; i < 128 * 8; i += 256) {
            int r = i >> 3, c = i & 7;
            int node = bn + r;
            float4 v = (node < NN)
                ? *(const float4*)&x[(size_t)node * DIN + kc + c * 4]
                : make_float4(0.f, 0.f, 0.f, 0.f);
            *(float4*)&xs[r * XS_STRIDE + c * 4] = v;
        }
        __syncthreads();
        #pragma unroll 8
        for (int kk = 0; kk < KC; kk++) {
            ulonglong2 wa = *(const ulonglong2*)&ws[(kc + kk) * HD + colq * 4];
            ulonglong2 wb = *(const ulonglong2*)&ws[(kc + kk) * HD + 32 + colq * 4];
            float x0 = xs[nr * XS_STRIDE + kk];
            float x1 = xs[(nr + 32) * XS_STRIDE + kk];
            float x2 = xs[(nr + 64) * XS_STRIDE + kk];
            float x3 = xs[(nr + 96) * XS_STRIDE + kk];
            u64 X0 = packf2(x0, x0), X1 = packf2(x1, x1);
            u64 X2 = packf2(x2, x2), X3 = packf2(x3, x3);
            ffma2(accA[0][0], X0, wa.x); ffma2(accA[0][1], X0, wa.y);
            ffma2(accB[0][0], X0, wb.x); ffma2(accB[0][1], X0, wb.y);
            ffma2(accA[1][0], X1, wa.x); ffma2(accA[1][1], X1, wa.y);
            ffma2(accB[1][0], X1, wb.x); ffma2(accB[1][1], X1, wb.y);
            ffma2(accA[2][0], X2, wa.x); ffma2(accA[2][1], X2, wa.y);
            ffma2(accB[2][0], X2, wb.x); ffma2(accB[2][1], X2, wb.y);
            ffma2(accA[3][0], X3, wa.x); ffma2(accA[3][1], X3, wa.y);
            ffma2(accB[3][0], X3, wb.x); ffma2(accB[3][1], X3, wb.y);
        }
    }
    int hA = colq >> 2;
    int hB = 2 + hA;
    int woff = (colq & 3) * 4;
    float4 sA = *(const float4*)&a_src[hA * HID + woff];
    float4 dA = *(const float4*)&a_dst[hA * HID + woff];
    float4 sB = *(const float4*)&a_src[hB * HID + woff];
    float4 dB = *(const float4*)&a_dst[hB * HID + woff];
    #pragma unroll
    for (int i = 0; i < 4; i++) {
        int node = bn + nr + i * 32;
        bool ok = node < NN;
        float2 a01 = unpackf2(accA[i][0]);
        float2 a23 = unpackf2(accA[i][1]);
        float2 b01 = unpackf2(accB[i][0]);
        float2 b23 = unpackf2(accB[i][1]);
        if (ok) {
            __half2 pa0 = __floats2half2_rn(a01.x, a01.y);
            __half2 pa1 = __floats2half2_rn(a23.x, a23.y);
            __half2 pb0 = __floats2half2_rn(b01.x, b01.y);
            __half2 pb1 = __floats2half2_rn(b23.x, b23.y);
            *(uint2*)&g_h1h[(size_t)node * HD + colq * 4]      = make_uint2(*(unsigned*)&pa0, *(unsigned*)&pa1);
            *(uint2*)&g_h1h[(size_t)node * HD + 32 + colq * 4] = make_uint2(*(unsigned*)&pb0, *(unsigned*)&pb1);
        }
        float psA = a01.x*sA.x + a01.y*sA.y + a23.x*sA.z + a23.y*sA.w;
        float pdA = a01.x*dA.x + a01.y*dA.y + a23.x*dA.z + a23.y*dA.w;
        float psB = b01.x*sB.x + b01.y*sB.y + b23.x*sB.z + b23.y*sB.w;
        float pdB = b01.x*dB.x + b01.y*dB.y + b23.x*dB.z + b23.y*dB.w;
        #pragma unroll
        for (int off = 1; off < 4; off <<= 1) {
            psA += __shfl_xor_sync(FULLM, psA, off);
            pdA += __shfl_xor_sync(FULLM, pdA, off);
            psB += __shfl_xor_sync(FULLM, psB, off);
            pdB += __shfl_xor_sync(FULLM, pdB, off);
        }
        if (((colq & 3) == 0) && ok) {
            g_als1[node * 4 + hA] = psA;
            g_ald1[node * 4 + hA] = pdA;
            g_als1[node * 4 + hB] = psB;
            g_ald1[node * 4 + hB] = pdB;
        }
    }
}

// ---------------- FUSED gather1: quarter-warp, 4 edges per LDG -------------
// qe = lane>>3 selects edge slot; m = lane&7 owns channels 8m..8m+7 (uint4),
// all inside head m>>1.
__global__ void gather1_fused_kernel(const float* __restrict__ b1,
                                     const float* __restrict__ W2,
                                     const float* __restrict__ a_src2,
                                     const float* __restrict__ a_dst2) {
    int n = (blockIdx.x * blockDim.x + threadIdx.x) >> 5;
    if (n >= NN) return;
    int lane = threadIdx.x & 31;
    int m = lane & 7, qe = lane >> 3;
    int myh = m >> 1;
    float ad = g_ald1[n * 4 + myh];
    float ax[8];
    #pragma unroll
    for (int i = 0; i < 8; i++) ax[i] = 0.f;
    float z = 0.f;
    if (qe == 0) {  // self loop counted once
        float w = lrelu_exp(g_als1[n * 4 + myh] + ad);
        z += w;
        uint4 u = *(const uint4*)&g_h1h[(size_t)n * HD + m * 8];
        float2 p0 = __half22float2(*(__half2*)&u.x);
        float2 p1 = __half22float2(*(__half2*)&u.y);
        float2 p2 = __half22float2(*(__half2*)&u.z);
        float2 p3 = __half22float2(*(__half2*)&u.w);
        ax[0] += p0.x*w; ax[1] += p0.y*w; ax[2] += p1.x*w; ax[3] += p1.y*w;
        ax[4] += p2.x*w; ax[5] += p2.y*w; ax[6] += p3.x*w; ax[7] += p3.y*w;
    }
    int e = g_indptr[n], end = g_indptr[n + 1];
    for (; e + 8 <= end; e += 8) {
        int s0 = g_indices[e + qe];
        int s1 = g_indices[e + 4 + qe];
        float l0 = g_als1[s0 * 4 + myh], l1 = g_als1[s1 * 4 + myh];
        uint4 u0 = *(const uint4*)&g_h1h[(size_t)s0 * HD + m * 8];
        uint4 u1 = *(const uint4*)&g_h1h[(size_t)s1 * HD + m * 8];
        float w0 = lrelu_exp(l0 + ad), w1 = lrelu_exp(l1 + ad);
        z += w0 + w1;
        float2 q0 = __half22float2(*(__half2*)&u0.x), r0 = __half22float2(*(__half2*)&u1.x);
        float2 q1 = __half22float2(*(__half2*)&u0.y), r1 = __half22float2(*(__half2*)&u1.y);
        float2 q2 = __half22float2(*(__half2*)&u0.z), r2 = __half22float2(*(__half2*)&u1.z);
        float2 q3 = __half22float2(*(__half2*)&u0.w), r3 = __half22float2(*(__half2*)&u1.w);
        ax[0] += q0.x*w0 + r0.x*w1; ax[1] += q0.y*w0 + r0.y*w1;
        ax[2] += q1.x*w0 + r1.x*w1; ax[3] += q1.y*w0 + r1.y*w1;
        ax[4] += q2.x*w0 + r2.x*w1; ax[5] += q2.y*w0 + r2.y*w1;
        ax[6] += q3.x*w0 + r3.x*w1; ax[7] += q3.y*w0 + r3.y*w1;
    }
    for (; e < end; e += 4) {
        bool valid = (e + qe) < end;
        int s = valid ? g_indices[e + qe] : 0;
        float l = g_als1[s * 4 + myh];
        uint4 u = *(const uint4*)&g_h1h[(size_t)s * HD + m * 8];
        float w = valid ? lrelu_exp(l + ad) : 0.f;
        z += w;
        float2 p0 = __half22float2(*(__half2*)&u.x);
        float2 p1 = __half22float2(*(__half2*)&u.y);
        float2 p2 = __half22float2(*(__half2*)&u.z);
        float2 p3 = __half22float2(*(__half2*)&u.w);
        ax[0] += p0.x*w; ax[1] += p0.y*w; ax[2] += p1.x*w; ax[3] += p1.y*w;
        ax[4] += p2.x*w; ax[5] += p2.y*w; ax[6] += p3.x*w; ax[7] += p3.y*w;
    }
    // combine the four quarter-warps (lanes with equal m)
    #pragma unroll
    for (int i = 0; i < 8; i++) {
        ax[i] += __shfl_xor_sync(FULLM, ax[i], 8);
        ax[i] += __shfl_xor_sync(FULLM, ax[i], 16);
    }
    z += __shfl_xor_sync(FULLM, z, 8);
    z += __shfl_xor_sync(FULLM, z, 16);
    float zi = 1.f / (z + 1e-16f);
    float4 bb0 = *(const float4*)&b1[m * 8];
    float4 bb1 = *(const float4*)&b1[m * 8 + 4];
    float f[8];
    f[0] = ax[0]*zi + bb0.x; f[1] = ax[1]*zi + bb0.y;
    f[2] = ax[2]*zi + bb0.z; f[3] = ax[3]*zi + bb0.w;
    f[4] = ax[4]*zi + bb1.x; f[5] = ax[5]*zi + bb1.y;
    f[6] = ax[6]*zi + bb1.z; f[7] = ax[7]*zi + bb1.w;
    #pragma unroll
    for (int i = 0; i < 8; i++) f[i] = f[i] > 0.f ? f[i] : expm1f(f[i]);  // ELU
    // ---- fused GEMV: t = feat @ W2, lane computes output channel `lane` ----
    float t = 0.f;
    #pragma unroll
    for (int k = 0; k < 8; k++) {
        #pragma unroll
        for (int j = 0; j < 8; j++) {
            float g = __shfl_sync(FULLM, f[j], k);   // feat channel 8k+j
            t += g * __ldg(&W2[(8 * k + j) * DOUT + lane]);
        }
    }
    g_t2h[(size_t)n * DOUT + lane] = __float2half_rn(t);
    // ---- fused als2/ald2 (fp32 exact) ----
    float ps = t * __ldg(&a_src2[lane]);
    float pd = t * __ldg(&a_dst2[lane]);
    #pragma unroll
    for (int off = 16; off > 0; off >>= 1) {
        ps += __shfl_xor_sync(FULLM, ps, off);
        pd += __shfl_xor_sync(FULLM, pd, off);
    }
    if (lane == 0) { g_als2[n] = ps; g_ald2[n] = pd; }
}

// ---------------- gather2: quarter-warp, 4 edges per LDG, writes d_out -----
// qe = lane>>3; m = lane&7 owns channels 4m..4m+3 (uint2 of half2s).
__global__ void gather2_kernel(float* __restrict__ out, const float* __restrict__ b2) {
    int n = (blockIdx.x * blockDim.x + threadIdx.x) >> 5;
    if (n >= NN) return;
    int lane = threadIdx.x & 31;
    int m = lane & 7, qe = lane >> 3;
    float ad = g_ald2[n];
    float a0 = 0.f, a1 = 0.f, a2 = 0.f, a3 = 0.f, z = 0.f;
    if (qe == 0) {  // self loop counted once
        float w = lrelu_exp(g_als2[n] + ad);
        z += w;
        uint2 u = *(const uint2*)&g_t2h[(size_t)n * DOUT + m * 4];
        float2 p0 = __half22float2(*(__half2*)&u.x);
        float2 p1 = __half22float2(*(__half2*)&u.y);
        a0 += p0.x*w; a1 += p0.y*w; a2 += p1.x*w; a3 += p1.y*w;
    }
    int e = g_indptr[n], end = g_indptr[n + 1];
    for (; e + 8 <= end; e += 8) {
        int s0 = g_indices[e + qe];
        int s1 = g_indices[e + 4 + qe];
        float l0 = g_als2[s0], l1 = g_als2[s1];
        uint2 u0 = *(const uint2*)&g_t2h[(size_t)s0 * DOUT + m * 4];
        uint2 u1 = *(const uint2*)&g_t2h[(size_t)s1 * DOUT + m * 4];
        float w0 = lrelu_exp(l0 + ad), w1 = lrelu_exp(l1 + ad);
        z += w0 + w1;
        float2 q0 = __half22float2(*(__half2*)&u0.x), r0 = __half22float2(*(__half2*)&u1.x);
        float2 q1 = __half22float2(*(__half2*)&u0.y), r1 = __half22float2(*(__half2*)&u1.y);
        a0 += q0.x*w0 + r0.x*w1; a1 += q0.y*w0 + r0.y*w1;
        a2 += q1.x*w0 + r1.x*w1; a3 += q1.y*w0 + r1.y*w1;
    }
    for (; e < end; e += 4) {
        bool valid = (e + qe) < end;
        int s = valid ? g_indices[e + qe] : 0;
        float l = g_als2[s];
        uint2 u = *(const uint2*)&g_t2h[(size_t)s * DOUT + m * 4];
        float w = valid ? lrelu_exp(l + ad) : 0.f;
        z += w;
        float2 p0 = __half22float2(*(__half2*)&u.x);
        float2 p1 = __half22float2(*(__half2*)&u.y);
        a0 += p0.x*w; a1 += p0.y*w; a2 += p1.x*w; a3 += p1.y*w;
    }
    a0 += __shfl_xor_sync(FULLM, a0, 8);  a0 += __shfl_xor_sync(FULLM, a0, 16);
    a1 += __shfl_xor_sync(FULLM, a1, 8);  a1 += __shfl_xor_sync(FULLM, a1, 16);
    a2 += __shfl_xor_sync(FULLM, a2, 8);  a2 += __shfl_xor_sync(FULLM, a2, 16);
    a3 += __shfl_xor_sync(FULLM, a3, 8);  a3 += __shfl_xor_sync(FULLM, a3, 16);
    z  += __shfl_xor_sync(FULLM, z, 8);   z  += __shfl_xor_sync(FULLM, z, 16);
    if (qe == 0) {
        float zi = 1.f / (z + 1e-16f);
        float4 bb = *(const float4*)&b2[m * 4];
        *(float4*)&out[(size_t)n * DOUT + m * 4] =
            make_float4(a0 * zi + bb.x, a1 * zi + bb.y, a2 * zi + bb.z, a3 * zi + bb.w);
    }
}

// ---------------------------------------------------------------------------
extern "C" void kernel_launch(void* const* d_in, const int* in_sizes, int n_in,
                              void* d_out, int out_size) {
    const float*     x      = (const float*)d_in[0];
    const long long* ei     = (const long long*)d_in[1];
    const float*     W1     = (const float*)d_in[2];
    const float*     a_src1 = (const float*)d_in[3];
    const float*     a_dst1 = (const float*)d_in[4];
    const float*     b1     = (const float*)d_in[5];
    const float*     W2     = (const float*)d_in[6];
    const float*     a_src2 = (const float*)d_in[7];
    const float*     a_dst2 = (const float*)d_in[8];
    const float*     b2     = (const float*)d_in[9];
    float* out = (float*)d_out;

    const int NB = (NN + 255) / 256;
    const int GB = (NN + 127) / 128;
    const int E2 = (EE / 2 + 255) / 256;
    const int WB = (NN * 32 + 255) / 256;

    // zero degree counters via memset node (not a kernel launch)
    void* cntPtr = nullptr;
    cudaGetSymbolAddress(&cntPtr, g_cnt);
    cudaMemsetAsync(cntPtr, 0, NN * sizeof(int), 0);

    cudaEventRecord(g_evFork, 0);
    cudaStreamWaitEvent(g_s2, g_evFork, 0);

    detect_kernel<<<1, 32>>>(ei);
    convert_count_kernel<<<E2, 256>>>(ei);
    scan1_kernel<<<NBLK, 1024>>>();
    gemm1_kernel<<<GB, 256, G1_SMEM, g_s2>>>(x, W1, a_src1, a_dst1);
    cudaEventRecord(g_evJoin, g_s2);
    scan23_kernel<<<NB, 256>>>();
    scatter_kernel<<<E2, 256>>>();

    cudaStreamWaitEvent(0, g_evJoin, 0);
    gather1_fused_kernel<<<WB, 256>>>(b1, W2, a_src2, a_dst2);
    gather2_kernel<<<WB, 256>>>(out, b2);
}

// round 13
// speedup vs baseline: 1.1619x; 1.1619x over previous
#include <cuda_runtime.h>
#include <cuda_fp16.h>
#include <math.h>

#define NN   100000
#define EE   1600000
#define DIN  128
#define HD   64      // HEADS*HID
#define HEADS 4
#define HID  16
#define DOUT 32
#define NEG  0.2f
#define NBLK ((NN + 1023) / 1024)   // scan blocks = 98
#define KC   32                      // k-chunk
#define XS_STRIDE 36
#define G1_SMEM ((DIN * HD + 128 * XS_STRIDE) * 4)   // 51200 B
#define FULLM 0xffffffffu

typedef unsigned long long u64;

// ---------------- scratch (device globals; no allocation allowed) ----------
__device__ __align__(16) __half g_h1h[NN * HD];     // x @ W1   (fp16 storage)
__device__ __align__(16) float g_als1[NN * HEADS];
__device__ __align__(16) float g_ald1[NN * HEADS];
__device__ __align__(16) __half g_t2h[NN * DOUT];   // feat1 @ W2 (fp16 storage)
__device__ __align__(16) float g_als2[NN];
__device__ __align__(16) float g_ald2[NN];
// CSR scratch
__device__ __align__(16) int g_src[EE];
__device__ __align__(16) int g_dst[EE];
__device__ __align__(16) int g_rank[EE];            // per-dst arrival rank
__device__ int g_cnt[NN];
__device__ int g_indptr[NN + 1];
__device__ int g_indices[EE];
__device__ int g_bsum[NBLK];
__device__ int g_is64;

__global__ void gemm1_kernel(const float*, const float*, const float*, const float*);

// ---------------- stream/event for fork-join overlap (created pre-main) ----
static cudaStream_t g_s2;
static cudaEvent_t g_evFork, g_evJoin;
static struct Boot {
    Boot() {
        cudaStreamCreateWithFlags(&g_s2, cudaStreamNonBlocking);
        cudaEventCreateWithFlags(&g_evFork, cudaEventDisableTiming);
        cudaEventCreateWithFlags(&g_evJoin, cudaEventDisableTiming);
        cudaFuncSetAttribute(gemm1_kernel,
                             cudaFuncAttributeMaxDynamicSharedMemorySize, G1_SMEM);
    }
} g_boot;

__device__ __forceinline__ float lrelu_exp(float l) {
    l = fmaxf(l, NEG * l);                // branchless leaky relu
    return __expf(fminf(l, 25.f));        // clamp is a no-op safety net
}

// ---- packed fp32x2 helpers (sm_103a FFMA2 path; exact fp32 rounding) ------
__device__ __forceinline__ u64 packf2(float a, float b) {
    u64 r; asm("mov.b64 %0, {%1, %2};" : "=l"(r) : "f"(a), "f"(b)); return r;
}
__device__ __forceinline__ void ffma2(u64& d, u64 a, u64 b) {
    asm("fma.rn.f32x2 %0, %1, %2, %0;" : "+l"(d) : "l"(a), "l"(b));
}
__device__ __forceinline__ float2 unpackf2(u64 v) {
    float2 r; asm("mov.b64 {%0, %1}, %2;" : "=f"(r.x), "=f"(r.y) : "l"(v)); return r;
}

// ---------------- detect dtype (1 warp) ------------------------------------
__global__ void detect_kernel(const long long* ei) {
    if (threadIdx.x == 0) {
        int ok = 1;
        for (int k = 0; k < 64; k++) {
            long long v = ei[k];
            if (v < 0 || v >= NN) { ok = 0; break; }
        }
        g_is64 = ok;
    }
}

// ---------------- convert + count + rank (2 edges/thread) ------------------
__global__ void convert_count_kernel(const long long* __restrict__ ei) {
    int e = (blockIdx.x * blockDim.x + threadIdx.x) * 2;
    if (e >= EE) return;
    int s0, s1, d0, d1;
    if (g_is64) {
        longlong2 sv = *(const longlong2*)&ei[e];
        longlong2 dv = *(const longlong2*)&ei[e + EE];
        s0 = (int)sv.x; s1 = (int)sv.y; d0 = (int)dv.x; d1 = (int)dv.y;
    } else {
        const int* p = (const int*)ei;
        int2 sv = *(const int2*)&p[e];
        int2 dv = *(const int2*)&p[e + EE];
        s0 = sv.x; s1 = sv.y; d0 = dv.x; d1 = dv.y;
    }
    *(int2*)&g_src[e] = make_int2(s0, s1);
    *(int2*)&g_dst[e] = make_int2(d0, d1);
    int r0 = atomicAdd(&g_cnt[d0], 1);
    int r1 = atomicAdd(&g_cnt[d1], 1);
    *(int2*)&g_rank[e] = make_int2(r0, r1);
}

// ---------------- scan phase 1: per-block exclusive scan -------------------
__global__ void scan1_kernel() {
    __shared__ int wsum[32];
    int t = threadIdx.x;
    int i = blockIdx.x * 1024 + t;
    int v = (i < NN) ? g_cnt[i] : 0;
    int lane = t & 31, wid = t >> 5;
    int p = v;
    #pragma unroll
    for (int off = 1; off < 32; off <<= 1) {
        int a = __shfl_up_sync(FULLM, p, off);
        if (lane >= off) p += a;
    }
    if (lane == 31) wsum[wid] = p;
    __syncthreads();
    if (wid == 0) {
        int s = wsum[lane];
        #pragma unroll
        for (int off = 1; off < 32; off <<= 1) {
            int a = __shfl_up_sync(FULLM, s, off);
            if (lane >= off) s += a;
        }
        wsum[lane] = s;
    }
    __syncthreads();
    int base = (wid > 0) ? wsum[wid - 1] : 0;
    int incl = p + base;
    if (i < NN) g_indptr[i] = incl - v;      // exclusive within block
    if (t == 1023) g_bsum[blockIdx.x] = incl;
}

// ---------------- scan phase 2+3 merged ------------------------------------
__global__ void scan23_kernel() {
    int i = blockIdx.x * blockDim.x + threadIdx.x;
    int j = (int)((blockIdx.x * blockDim.x) >> 10);
    int lane = threadIdx.x & 31;
    int acc = 0;
    for (int k = lane; k < j; k += 32) acc += g_bsum[k];
    #pragma unroll
    for (int off = 16; off > 0; off >>= 1)
        acc += __shfl_xor_sync(FULLM, acc, off);
    if (i < NN) g_indptr[i] += acc;
    if (i == 0) g_indptr[NN] = EE;
}

// ---------------- CSR scatter: 2 edges/thread, rank precomputed ------------
__global__ void scatter_kernel() {
    int e = (blockIdx.x * blockDim.x + threadIdx.x) * 2;
    if (e >= EE) return;
    int2 s = *(const int2*)&g_src[e];
    int2 d = *(const int2*)&g_dst[e];
    int2 r = *(const int2*)&g_rank[e];
    g_indices[g_indptr[d.x] + r.x] = s.x;
    g_indices[g_indptr[d.y] + r.y] = s.y;
}

// ---------------- GEMM1 (smem W, chunked xs, packed FFMA2) + als1/ald1 -----
__global__ __launch_bounds__(256, 4)
void gemm1_kernel(const float* __restrict__ x, const float* __restrict__ W,
                  const float* __restrict__ a_src, const float* __restrict__ a_dst) {
    extern __shared__ float sm[];
    float* ws = sm;                         // [128][64]
    float* xs = sm + DIN * HD;              // [128][XS_STRIDE]
    int t = threadIdx.x;
    int bn = blockIdx.x * 128;
    for (int i = t; i < DIN * HD / 4; i += 256)
        ((float4*)ws)[i] = ((const float4*)W)[i];

    int colq = t & 7;
    int nr   = t >> 3;
    u64 accA[4][2], accB[4][2];
    #pragma unroll
    for (int i = 0; i < 4; i++) {
        accA[i][0] = accA[i][1] = 0ULL;
        accB[i][0] = accB[i][1] = 0ULL;
    }
    for (int kc = 0; kc < DIN; kc += KC) {
        __syncthreads();
        #pragma unroll
        for (int i = t; i < 128 * 8; i += 256) {
            int r = i >> 3, c = i & 7;
            int node = bn + r;
            float4 v = (node < NN)
                ? *(const float4*)&x[(size_t)node * DIN + kc + c * 4]
                : make_float4(0.f, 0.f, 0.f, 0.f);
            *(float4*)&xs[r * XS_STRIDE + c * 4] = v;
        }
        __syncthreads();
        #pragma unroll 8
        for (int kk = 0; kk < KC; kk++) {
            ulonglong2 wa = *(const ulonglong2*)&ws[(kc + kk) * HD + colq * 4];
            ulonglong2 wb = *(const ulonglong2*)&ws[(kc + kk) * HD + 32 + colq * 4];
            float x0 = xs[nr * XS_STRIDE + kk];
            float x1 = xs[(nr + 32) * XS_STRIDE + kk];
            float x2 = xs[(nr + 64) * XS_STRIDE + kk];
            float x3 = xs[(nr + 96) * XS_STRIDE + kk];
            u64 X0 = packf2(x0, x0), X1 = packf2(x1, x1);
            u64 X2 = packf2(x2, x2), X3 = packf2(x3, x3);
            ffma2(accA[0][0], X0, wa.x); ffma2(accA[0][1], X0, wa.y);
            ffma2(accB[0][0], X0, wb.x); ffma2(accB[0][1], X0, wb.y);
            ffma2(accA[1][0], X1, wa.x); ffma2(accA[1][1], X1, wa.y);
            ffma2(accB[1][0], X1, wb.x); ffma2(accB[1][1], X1, wb.y);
            ffma2(accA[2][0], X2, wa.x); ffma2(accA[2][1], X2, wa.y);
            ffma2(accB[2][0], X2, wb.x); ffma2(accB[2][1], X2, wb.y);
            ffma2(accA[3][0], X3, wa.x); ffma2(accA[3][1], X3, wa.y);
            ffma2(accB[3][0], X3, wb.x); ffma2(accB[3][1], X3, wb.y);
        }
    }
    int hA = colq >> 2;
    int hB = 2 + hA;
    int woff = (colq & 3) * 4;
    float4 sA = *(const float4*)&a_src[hA * HID + woff];
    float4 dA = *(const float4*)&a_dst[hA * HID + woff];
    float4 sB = *(const float4*)&a_src[hB * HID + woff];
    float4 dB = *(const float4*)&a_dst[hB * HID + woff];
    #pragma unroll
    for (int i = 0; i < 4; i++) {
        int node = bn + nr + i * 32;
        bool ok = node < NN;
        float2 a01 = unpackf2(accA[i][0]);
        float2 a23 = unpackf2(accA[i][1]);
        float2 b01 = unpackf2(accB[i][0]);
        float2 b23 = unpackf2(accB[i][1]);
        if (ok) {
            __half2 pa0 = __floats2half2_rn(a01.x, a01.y);
            __half2 pa1 = __floats2half2_rn(a23.x, a23.y);
            __half2 pb0 = __floats2half2_rn(b01.x, b01.y);
            __half2 pb1 = __floats2half2_rn(b23.x, b23.y);
            *(uint2*)&g_h1h[(size_t)node * HD + colq * 4]      = make_uint2(*(unsigned*)&pa0, *(unsigned*)&pa1);
            *(uint2*)&g_h1h[(size_t)node * HD + 32 + colq * 4] = make_uint2(*(unsigned*)&pb0, *(unsigned*)&pb1);
        }
        float psA = a01.x*sA.x + a01.y*sA.y + a23.x*sA.z + a23.y*sA.w;
        float pdA = a01.x*dA.x + a01.y*dA.y + a23.x*dA.z + a23.y*dA.w;
        float psB = b01.x*sB.x + b01.y*sB.y + b23.x*sB.z + b23.y*sB.w;
        float pdB = b01.x*dB.x + b01.y*dB.y + b23.x*dB.z + b23.y*dB.w;
        #pragma unroll
        for (int off = 1; off < 4; off <<= 1) {
            psA += __shfl_xor_sync(FULLM, psA, off);
            pdA += __shfl_xor_sync(FULLM, pdA, off);
            psB += __shfl_xor_sync(FULLM, psB, off);
            pdB += __shfl_xor_sync(FULLM, pdB, off);
        }
        if (((colq & 3) == 0) && ok) {
            g_als1[node * 4 + hA] = psA;
            g_ald1[node * 4 + hA] = pdA;
            g_als1[node * 4 + hB] = psB;
            g_ald1[node * 4 + hB] = pdB;
        }
    }
}

// ---------------- FUSED gather1: 2 nodes/warp (half-warp per node) ---------
// half = lane>>4 selects node (2w+half); within half: m = lane&7 owns
// channels 8m..8m+7 (uint4, head m>>1), le = (lane>>3)&1 = edge parity.
__global__ void gather1_fused_kernel(const float* __restrict__ b1,
                                     const float* __restrict__ W2,
                                     const float* __restrict__ a_src2,
                                     const float* __restrict__ a_dst2) {
    int w = (blockIdx.x * blockDim.x + threadIdx.x) >> 5;
    if (w * 2 >= NN) return;
    int lane = threadIdx.x & 31;
    int half = lane >> 4;
    int hl = lane & 15, m = hl & 7, le = hl >> 3;
    int n = 2 * w + half;                    // NN is even -> always valid
    int myh = m >> 1;
    float ad = g_ald1[n * 4 + myh];
    float ax[8];
    #pragma unroll
    for (int i = 0; i < 8; i++) ax[i] = 0.f;
    float z = 0.f;
    if (le == 0) {  // self loop counted once per node
        float w0 = lrelu_exp(g_als1[n * 4 + myh] + ad);
        z += w0;
        uint4 u = *(const uint4*)&g_h1h[(size_t)n * HD + m * 8];
        float2 p0 = __half22float2(*(__half2*)&u.x);
        float2 p1 = __half22float2(*(__half2*)&u.y);
        float2 p2 = __half22float2(*(__half2*)&u.z);
        float2 p3 = __half22float2(*(__half2*)&u.w);
        ax[0] += p0.x*w0; ax[1] += p0.y*w0; ax[2] += p1.x*w0; ax[3] += p1.y*w0;
        ax[4] += p2.x*w0; ax[5] += p2.y*w0; ax[6] += p3.x*w0; ax[7] += p3.y*w0;
    }
    int e = g_indptr[n], end = g_indptr[n + 1];
    while (__any_sync(FULLM, e + 8 <= end)) {
        if (e + 8 <= end) {
            int s0 = g_indices[e + le];
            int s1 = g_indices[e + 2 + le];
            int s2 = g_indices[e + 4 + le];
            int s3 = g_indices[e + 6 + le];
            float l0 = g_als1[s0 * 4 + myh], l1 = g_als1[s1 * 4 + myh];
            float l2 = g_als1[s2 * 4 + myh], l3 = g_als1[s3 * 4 + myh];
            uint4 u0 = *(const uint4*)&g_h1h[(size_t)s0 * HD + m * 8];
            uint4 u1 = *(const uint4*)&g_h1h[(size_t)s1 * HD + m * 8];
            uint4 u2 = *(const uint4*)&g_h1h[(size_t)s2 * HD + m * 8];
            uint4 u3 = *(const uint4*)&g_h1h[(size_t)s3 * HD + m * 8];
            float w0 = lrelu_exp(l0 + ad), w1 = lrelu_exp(l1 + ad);
            float w2 = lrelu_exp(l2 + ad), w3 = lrelu_exp(l3 + ad);
            z += (w0 + w1) + (w2 + w3);
            float2 q0 = __half22float2(*(__half2*)&u0.x), q1 = __half22float2(*(__half2*)&u0.y);
            float2 q2 = __half22float2(*(__half2*)&u0.z), q3 = __half22float2(*(__half2*)&u0.w);
            float2 r0 = __half22float2(*(__half2*)&u1.x), r1 = __half22float2(*(__half2*)&u1.y);
            float2 r2 = __half22float2(*(__half2*)&u1.z), r3 = __half22float2(*(__half2*)&u1.w);
            float2 t0 = __half22float2(*(__half2*)&u2.x), t1 = __half22float2(*(__half2*)&u2.y);
            float2 t2 = __half22float2(*(__half2*)&u2.z), t3 = __half22float2(*(__half2*)&u2.w);
            float2 v0 = __half22float2(*(__half2*)&u3.x), v1 = __half22float2(*(__half2*)&u3.y);
            float2 v2 = __half22float2(*(__half2*)&u3.z), v3 = __half22float2(*(__half2*)&u3.w);
            ax[0] += q0.x*w0 + r0.x*w1 + t0.x*w2 + v0.x*w3;
            ax[1] += q0.y*w0 + r0.y*w1 + t0.y*w2 + v0.y*w3;
            ax[2] += q1.x*w0 + r1.x*w1 + t1.x*w2 + v1.x*w3;
            ax[3] += q1.y*w0 + r1.y*w1 + t1.y*w2 + v1.y*w3;
            ax[4] += q2.x*w0 + r2.x*w1 + t2.x*w2 + v2.x*w3;
            ax[5] += q2.y*w0 + r2.y*w1 + t2.y*w2 + v2.y*w3;
            ax[6] += q3.x*w0 + r3.x*w1 + t3.x*w2 + v3.x*w3;
            ax[7] += q3.y*w0 + r3.y*w1 + t3.y*w2 + v3.y*w3;
            e += 8;
        }
    }
    while (__any_sync(FULLM, e < end)) {
        bool valid = (e + le) < end;
        if (valid) {
            int s = g_indices[e + le];
            float l = g_als1[s * 4 + myh];
            uint4 u = *(const uint4*)&g_h1h[(size_t)s * HD + m * 8];
            float w0 = lrelu_exp(l + ad);
            z += w0;
            float2 p0 = __half22float2(*(__half2*)&u.x);
            float2 p1 = __half22float2(*(__half2*)&u.y);
            float2 p2 = __half22float2(*(__half2*)&u.z);
            float2 p3 = __half22float2(*(__half2*)&u.w);
            ax[0] += p0.x*w0; ax[1] += p0.y*w0; ax[2] += p1.x*w0; ax[3] += p1.y*w0;
            ax[4] += p2.x*w0; ax[5] += p2.y*w0; ax[6] += p3.x*w0; ax[7] += p3.y*w0;
        }
        e += 2;
    }
    // combine the two le slots within each half
    #pragma unroll
    for (int i = 0; i < 8; i++) ax[i] += __shfl_xor_sync(FULLM, ax[i], 8);
    z += __shfl_xor_sync(FULLM, z, 8);
    float zi = 1.f / (z + 1e-16f);
    float4 bb0 = *(const float4*)&b1[m * 8];
    float4 bb1 = *(const float4*)&b1[m * 8 + 4];
    float f[8];
    f[0] = ax[0]*zi + bb0.x; f[1] = ax[1]*zi + bb0.y;
    f[2] = ax[2]*zi + bb0.z; f[3] = ax[3]*zi + bb0.w;
    f[4] = ax[4]*zi + bb1.x; f[5] = ax[5]*zi + bb1.y;
    f[6] = ax[6]*zi + bb1.z; f[7] = ax[7]*zi + bb1.w;
    #pragma unroll
    for (int i = 0; i < 8; i++) f[i] = f[i] > 0.f ? f[i] : expm1f(f[i]);  // ELU
    // ---- fused GEMV: lane (hl) computes output channels 2hl, 2hl+1 --------
    float t0 = 0.f, t1 = 0.f;
    int hb = lane & 16;   // half base for shfl source
    #pragma unroll
    for (int k = 0; k < 8; k++) {
        #pragma unroll
        for (int j = 0; j < 8; j++) {
            float g = __shfl_sync(FULLM, f[j], hb | k);   // feat channel 8k+j of my node
            float2 wv = __ldg(&((const float2*)W2)[(8 * k + j) * 16 + hl]);
            t0 += g * wv.x;
            t1 += g * wv.y;
        }
    }
    __half2 tp = __floats2half2_rn(t0, t1);
    *(__half2*)&g_t2h[(size_t)n * DOUT + hl * 2] = tp;
    // ---- fused als2/ald2 (fp32 exact), reduce within half -----------------
    float2 s2 = __ldg(&((const float2*)a_src2)[hl]);
    float2 d2 = __ldg(&((const float2*)a_dst2)[hl]);
    float ps = t0 * s2.x + t1 * s2.y;
    float pd = t0 * d2.x + t1 * d2.y;
    #pragma unroll
    for (int off = 1; off < 16; off <<= 1) {
        ps += __shfl_xor_sync(FULLM, ps, off);
        pd += __shfl_xor_sync(FULLM, pd, off);
    }
    if (hl == 0) { g_als2[n] = ps; g_ald2[n] = pd; }
}

// ---------------- gather2: 2 nodes/warp, writes d_out ----------------------
// half = lane>>4; within half: m = lane&7 owns channels 4m..4m+3 (uint2),
// le = (lane>>3)&1 = edge parity.
__global__ void gather2_kernel(float* __restrict__ out, const float* __restrict__ b2) {
    int w = (blockIdx.x * blockDim.x + threadIdx.x) >> 5;
    if (w * 2 >= NN) return;
    int lane = threadIdx.x & 31;
    int half = lane >> 4;
    int hl = lane & 15, m = hl & 7, le = hl >> 3;
    int n = 2 * w + half;
    float ad = g_ald2[n];
    float a0 = 0.f, a1 = 0.f, a2 = 0.f, a3 = 0.f, z = 0.f;
    if (le == 0) {  // self loop counted once per node
        float w0 = lrelu_exp(g_als2[n] + ad);
        z += w0;
        uint2 u = *(const uint2*)&g_t2h[(size_t)n * DOUT + m * 4];
        float2 p0 = __half22float2(*(__half2*)&u.x);
        float2 p1 = __half22float2(*(__half2*)&u.y);
        a0 += p0.x*w0; a1 += p0.y*w0; a2 += p1.x*w0; a3 += p1.y*w0;
    }
    int e = g_indptr[n], end = g_indptr[n + 1];
    while (__any_sync(FULLM, e + 8 <= end)) {
        if (e + 8 <= end) {
            int s0 = g_indices[e + le];
            int s1 = g_indices[e + 2 + le];
            int s2 = g_indices[e + 4 + le];
            int s3 = g_indices[e + 6 + le];
            float l0 = g_als2[s0], l1 = g_als2[s1], l2 = g_als2[s2], l3 = g_als2[s3];
            uint2 u0 = *(const uint2*)&g_t2h[(size_t)s0 * DOUT + m * 4];
            uint2 u1 = *(const uint2*)&g_t2h[(size_t)s1 * DOUT + m * 4];
            uint2 u2 = *(const uint2*)&g_t2h[(size_t)s2 * DOUT + m * 4];
            uint2 u3 = *(const uint2*)&g_t2h[(size_t)s3 * DOUT + m * 4];
            float w0 = lrelu_exp(l0 + ad), w1 = lrelu_exp(l1 + ad);
            float w2 = lrelu_exp(l2 + ad), w3 = lrelu_exp(l3 + ad);
            z += (w0 + w1) + (w2 + w3);
            float2 q0 = __half22float2(*(__half2*)&u0.x), q1 = __half22float2(*(__half2*)&u0.y);
            float2 r0 = __half22float2(*(__half2*)&u1.x), r1 = __half22float2(*(__half2*)&u1.y);
            float2 t0 = __half22float2(*(__half2*)&u2.x), t1 = __half22float2(*(__half2*)&u2.y);
            float2 v0 = __half22float2(*(__half2*)&u3.x), v1 = __half22float2(*(__half2*)&u3.y);
            a0 += q0.x*w0 + r0.x*w1 + t0.x*w2 + v0.x*w3;
            a1 += q0.y*w0 + r0.y*w1 + t0.y*w2 + v0.y*w3;
            a2 += q1.x*w0 + r1.x*w1 + t1.x*w2 + v1.x*w3;
            a3 += q1.y*w0 + r1.y*w1 + t1.y*w2 + v1.y*w3;
            e += 8;
        }
    }
    while (__any_sync(FULLM, e < end)) {
        bool valid = (e + le) < end;
        if (valid) {
            int s = g_indices[e + le];
            float l = g_als2[s];
            uint2 u = *(const uint2*)&g_t2h[(size_t)s * DOUT + m * 4];
            float w0 = lrelu_exp(l + ad);
            z += w0;
            float2 p0 = __half22float2(*(__half2*)&u.x);
            float2 p1 = __half22float2(*(__half2*)&u.y);
            a0 += p0.x*w0; a1 += p0.y*w0; a2 += p1.x*w0; a3 += p1.y*w0;
        }
        e += 2;
    }
    a0 += __shfl_xor_sync(FULLM, a0, 8);
    a1 += __shfl_xor_sync(FULLM, a1, 8);
    a2 += __shfl_xor_sync(FULLM, a2, 8);
    a3 += __shfl_xor_sync(FULLM, a3, 8);
    z  += __shfl_xor_sync(FULLM, z, 8);
    if (le == 0) {
        float zi = 1.f / (z + 1e-16f);
        float4 bb = *(const float4*)&b2[m * 4];
        *(float4*)&out[(size_t)n * DOUT + m * 4] =
            make_float4(a0 * zi + bb.x, a1 * zi + bb.y, a2 * zi + bb.z, a3 * zi + bb.w);
    }
}

// ---------------------------------------------------------------------------
extern "C" void kernel_launch(void* const* d_in, const int* in_sizes, int n_in,
                              void* d_out, int out_size) {
    const float*     x      = (const float*)d_in[0];
    const long long* ei     = (const long long*)d_in[1];
    const float*     W1     = (const float*)d_in[2];
    const float*     a_src1 = (const float*)d_in[3];
    const float*     a_dst1 = (const float*)d_in[4];
    const float*     b1     = (const float*)d_in[5];
    const float*     W2     = (const float*)d_in[6];
    const float*     a_src2 = (const float*)d_in[7];
    const float*     a_dst2 = (const float*)d_in[8];
    const float*     b2     = (const float*)d_in[9];
    float* out = (float*)d_out;

    const int NB = (NN + 255) / 256;
    const int GB = (NN + 127) / 128;
    const int E2 = (EE / 2 + 255) / 256;
    const int WB = ((NN / 2) * 32 + 255) / 256;   // 2 nodes per warp

    // zero degree counters via memset node (not a kernel launch)
    void* cntPtr = nullptr;
    cudaGetSymbolAddress(&cntPtr, g_cnt);
    cudaMemsetAsync(cntPtr, 0, NN * sizeof(int), 0);

    cudaEventRecord(g_evFork, 0);
    cudaStreamWaitEvent(g_s2, g_evFork, 0);

    detect_kernel<<<1, 32>>>(ei);
    convert_count_kernel<<<E2, 256>>>(ei);
    scan1_kernel<<<NBLK, 1024>>>();
    gemm1_kernel<<<GB, 256, G1_SMEM, g_s2>>>(x, W1, a_src1, a_dst1);
    cudaEventRecord(g_evJoin, g_s2);
    scan23_kernel<<<NB, 256>>>();
    scatter_kernel<<<E2, 256>>>();

    cudaStreamWaitEvent(0, g_evJoin, 0);
    gather1_fused_kernel<<<WB, 256>>>(b1, W2, a_src2, a_dst2);
    gather2_kernel<<<WB, 256>>>(out, b2);
}

// round 14
// speedup vs baseline: 1.2624x; 1.0865x over previous
#include <cuda_runtime.h>
#include <cuda_fp16.h>
#include <math.h>

#define NN   100000
#define EE   1600000
#define DIN  128
#define HD   64      // HEADS*HID
#define HEADS 4
#define HID  16
#define DOUT 32
#define NEG  0.2f
#define NBLK ((NN + 1023) / 1024)   // scan blocks = 98
#define KC   32                      // k-chunk
#define XS_STRIDE 36
#define G1_SMEM ((DIN * HD + 128 * XS_STRIDE) * 4)   // 51200 B
#define FULLM 0xffffffffu

typedef unsigned long long u64;

// ---------------- scratch (device globals; no allocation allowed) ----------
__device__ __align__(16) __half g_h1h[NN * HD];     // x @ W1   (fp16 storage)
__device__ __align__(16) float g_als1[NN * HEADS];
__device__ __align__(16) float g_ald1[NN * HEADS];
__device__ __align__(16) __half g_t2h[NN * DOUT];   // feat1 @ W2 (fp16 storage)
__device__ __align__(16) float g_als2[NN];
__device__ __align__(16) float g_ald2[NN];
// CSR scratch
__device__ __align__(16) int g_src[EE];
__device__ __align__(16) int g_dst[EE];
__device__ __align__(16) int g_rank[EE];            // per-dst arrival rank
__device__ int g_cnt[NN];
__device__ int g_indptr[NN + 1];
__device__ int g_indices[EE];
__device__ int g_bsum[NBLK];
__device__ int g_is64;

__global__ void gemm1_kernel(const float*, const float*, const float*, const float*);

// ---------------- stream/event for fork-join overlap (created pre-main) ----
static cudaStream_t g_s2;
static cudaEvent_t g_evFork, g_evJoin;
static struct Boot {
    Boot() {
        cudaStreamCreateWithFlags(&g_s2, cudaStreamNonBlocking);
        cudaEventCreateWithFlags(&g_evFork, cudaEventDisableTiming);
        cudaEventCreateWithFlags(&g_evJoin, cudaEventDisableTiming);
        cudaFuncSetAttribute(gemm1_kernel,
                             cudaFuncAttributeMaxDynamicSharedMemorySize, G1_SMEM);
    }
} g_boot;

__device__ __forceinline__ float lrelu_exp(float l) {
    l = fmaxf(l, NEG * l);                // branchless leaky relu
    return __expf(fminf(l, 25.f));        // clamp is a no-op safety net
}

// ---- packed fp32x2 helpers (sm_103a FFMA2 path; exact fp32 rounding) ------
__device__ __forceinline__ u64 packf2(float a, float b) {
    u64 r; asm("mov.b64 %0, {%1, %2};" : "=l"(r) : "f"(a), "f"(b)); return r;
}
__device__ __forceinline__ void ffma2(u64& d, u64 a, u64 b) {
    asm("fma.rn.f32x2 %0, %1, %2, %0;" : "+l"(d) : "l"(a), "l"(b));
}
__device__ __forceinline__ float2 unpackf2(u64 v) {
    float2 r; asm("mov.b64 {%0, %1}, %2;" : "=f"(r.x), "=f"(r.y) : "l"(v)); return r;
}

// ---------------- detect dtype (1 warp) ------------------------------------
__global__ void detect_kernel(const long long* ei) {
    if (threadIdx.x == 0) {
        int ok = 1;
        for (int k = 0; k < 64; k++) {
            long long v = ei[k];
            if (v < 0 || v >= NN) { ok = 0; break; }
        }
        g_is64 = ok;
    }
}

// ---------------- convert + count + rank (2 edges/thread) ------------------
__global__ void convert_count_kernel(const long long* __restrict__ ei) {
    int e = (blockIdx.x * blockDim.x + threadIdx.x) * 2;
    if (e >= EE) return;
    int s0, s1, d0, d1;
    if (g_is64) {
        longlong2 sv = *(const longlong2*)&ei[e];
        longlong2 dv = *(const longlong2*)&ei[e + EE];
        s0 = (int)sv.x; s1 = (int)sv.y; d0 = (int)dv.x; d1 = (int)dv.y;
    } else {
        const int* p = (const int*)ei;
        int2 sv = *(const int2*)&p[e];
        int2 dv = *(const int2*)&p[e + EE];
        s0 = sv.x; s1 = sv.y; d0 = dv.x; d1 = dv.y;
    }
    *(int2*)&g_src[e] = make_int2(s0, s1);
    *(int2*)&g_dst[e] = make_int2(d0, d1);
    int r0 = atomicAdd(&g_cnt[d0], 1);
    int r1 = atomicAdd(&g_cnt[d1], 1);
    *(int2*)&g_rank[e] = make_int2(r0, r1);
}

// ---------------- scan phase 1: per-block exclusive scan -------------------
__global__ void scan1_kernel() {
    __shared__ int wsum[32];
    int t = threadIdx.x;
    int i = blockIdx.x * 1024 + t;
    int v = (i < NN) ? g_cnt[i] : 0;
    int lane = t & 31, wid = t >> 5;
    int p = v;
    #pragma unroll
    for (int off = 1; off < 32; off <<= 1) {
        int a = __shfl_up_sync(FULLM, p, off);
        if (lane >= off) p += a;
    }
    if (lane == 31) wsum[wid] = p;
    __syncthreads();
    if (wid == 0) {
        int s = wsum[lane];
        #pragma unroll
        for (int off = 1; off < 32; off <<= 1) {
            int a = __shfl_up_sync(FULLM, s, off);
            if (lane >= off) s += a;
        }
        wsum[lane] = s;
    }
    __syncthreads();
    int base = (wid > 0) ? wsum[wid - 1] : 0;
    int incl = p + base;
    if (i < NN) g_indptr[i] = incl - v;      // exclusive within block
    if (t == 1023) g_bsum[blockIdx.x] = incl;
}

// ---------------- scan phase 2+3 merged ------------------------------------
__global__ void scan23_kernel() {
    int i = blockIdx.x * blockDim.x + threadIdx.x;
    int j = (int)((blockIdx.x * blockDim.x) >> 10);
    int lane = threadIdx.x & 31;
    int acc = 0;
    for (int k = lane; k < j; k += 32) acc += g_bsum[k];
    #pragma unroll
    for (int off = 16; off > 0; off >>= 1)
        acc += __shfl_xor_sync(FULLM, acc, off);
    if (i < NN) g_indptr[i] += acc;
    if (i == 0) g_indptr[NN] = EE;
}

// ---------------- CSR scatter: 2 edges/thread, rank precomputed ------------
__global__ void scatter_kernel() {
    int e = (blockIdx.x * blockDim.x + threadIdx.x) * 2;
    if (e >= EE) return;
    int2 s = *(const int2*)&g_src[e];
    int2 d = *(const int2*)&g_dst[e];
    int2 r = *(const int2*)&g_rank[e];
    g_indices[g_indptr[d.x] + r.x] = s.x;
    g_indices[g_indptr[d.y] + r.y] = s.y;
}

// ---------------- GEMM1 (smem W, chunked xs, packed FFMA2) + als1/ald1 -----
__global__ __launch_bounds__(256, 4)
void gemm1_kernel(const float* __restrict__ x, const float* __restrict__ W,
                  const float* __restrict__ a_src, const float* __restrict__ a_dst) {
    extern __shared__ float sm[];
    float* ws = sm;                         // [128][64]
    float* xs = sm + DIN * HD;              // [128][XS_STRIDE]
    int t = threadIdx.x;
    int bn = blockIdx.x * 128;
    for (int i = t; i < DIN * HD / 4; i += 256)
        ((float4*)ws)[i] = ((const float4*)W)[i];

    int colq = t & 7;
    int nr   = t >> 3;
    u64 accA[4][2], accB[4][2];
    #pragma unroll
    for (int i = 0; i < 4; i++) {
        accA[i][0] = accA[i][1] = 0ULL;
        accB[i][0] = accB[i][1] = 0ULL;
    }
    for (int kc = 0; kc < DIN; kc += KC) {
        __syncthreads();
        #pragma unroll
        for (int i = t; i < 128 * 8; i += 256) {
            int r = i >> 3, c = i & 7;
            int node = bn + r;
            float4 v = (node < NN)
                ? *(const float4*)&x[(size_t)node * DIN + kc + c * 4]
                : make_float4(0.f, 0.f, 0.f, 0.f);
            *(float4*)&xs[r * XS_STRIDE + c * 4] = v;
        }
        __syncthreads();
        #pragma unroll 8
        for (int kk = 0; kk < KC; kk++) {
            ulonglong2 wa = *(const ulonglong2*)&ws[(kc + kk) * HD + colq * 4];
            ulonglong2 wb = *(const ulonglong2*)&ws[(kc + kk) * HD + 32 + colq * 4];
            float x0 = xs[nr * XS_STRIDE + kk];
            float x1 = xs[(nr + 32) * XS_STRIDE + kk];
            float x2 = xs[(nr + 64) * XS_STRIDE + kk];
            float x3 = xs[(nr + 96) * XS_STRIDE + kk];
            u64 X0 = packf2(x0, x0), X1 = packf2(x1, x1);
            u64 X2 = packf2(x2, x2), X3 = packf2(x3, x3);
            ffma2(accA[0][0], X0, wa.x); ffma2(accA[0][1], X0, wa.y);
            ffma2(accB[0][0], X0, wb.x); ffma2(accB[0][1], X0, wb.y);
            ffma2(accA[1][0], X1, wa.x); ffma2(accA[1][1], X1, wa.y);
            ffma2(accB[1][0], X1, wb.x); ffma2(accB[1][1], X1, wb.y);
            ffma2(accA[2][0], X2, wa.x); ffma2(accA[2][1], X2, wa.y);
            ffma2(accB[2][0], X2, wb.x); ffma2(accB[2][1], X2, wb.y);
            ffma2(accA[3][0], X3, wa.x); ffma2(accA[3][1], X3, wa.y);
            ffma2(accB[3][0], X3, wb.x); ffma2(accB[3][1], X3, wb.y);
        }
    }
    int hA = colq >> 2;
    int hB = 2 + hA;
    int woff = (colq & 3) * 4;
    float4 sA = *(const float4*)&a_src[hA * HID + woff];
    float4 dA = *(const float4*)&a_dst[hA * HID + woff];
    float4 sB = *(const float4*)&a_src[hB * HID + woff];
    float4 dB = *(const float4*)&a_dst[hB * HID + woff];
    #pragma unroll
    for (int i = 0; i < 4; i++) {
        int node = bn + nr + i * 32;
        bool ok = node < NN;
        float2 a01 = unpackf2(accA[i][0]);
        float2 a23 = unpackf2(accA[i][1]);
        float2 b01 = unpackf2(accB[i][0]);
        float2 b23 = unpackf2(accB[i][1]);
        if (ok) {
            __half2 pa0 = __floats2half2_rn(a01.x, a01.y);
            __half2 pa1 = __floats2half2_rn(a23.x, a23.y);
            __half2 pb0 = __floats2half2_rn(b01.x, b01.y);
            __half2 pb1 = __floats2half2_rn(b23.x, b23.y);
            *(uint2*)&g_h1h[(size_t)node * HD + colq * 4]      = make_uint2(*(unsigned*)&pa0, *(unsigned*)&pa1);
            *(uint2*)&g_h1h[(size_t)node * HD + 32 + colq * 4] = make_uint2(*(unsigned*)&pb0, *(unsigned*)&pb1);
        }
        float psA = a01.x*sA.x + a01.y*sA.y + a23.x*sA.z + a23.y*sA.w;
        float pdA = a01.x*dA.x + a01.y*dA.y + a23.x*dA.z + a23.y*dA.w;
        float psB = b01.x*sB.x + b01.y*sB.y + b23.x*sB.z + b23.y*sB.w;
        float pdB = b01.x*dB.x + b01.y*dB.y + b23.x*dB.z + b23.y*dB.w;
        #pragma unroll
        for (int off = 1; off < 4; off <<= 1) {
            psA += __shfl_xor_sync(FULLM, psA, off);
            pdA += __shfl_xor_sync(FULLM, pdA, off);
            psB += __shfl_xor_sync(FULLM, psB, off);
            pdB += __shfl_xor_sync(FULLM, pdB, off);
        }
        if (((colq & 3) == 0) && ok) {
            g_als1[node * 4 + hA] = psA;
            g_ald1[node * 4 + hA] = pdA;
            g_als1[node * 4 + hB] = psB;
            g_ald1[node * 4 + hB] = pdB;
        }
    }
}

// ---------------- FUSED gather1: 4 nodes/warp (8-lane quarter per node) ----
// q = lane>>3 selects node 4w+q; m = lane&7 owns channels 8m..8m+7 (uint4,
// head m>>1). Single edge slot, 4-edge register batching. No combines needed.
__global__ void gather1_fused_kernel(const float* __restrict__ b1,
                                     const float* __restrict__ W2,
                                     const float* __restrict__ a_src2,
                                     const float* __restrict__ a_dst2) {
    int w = (blockIdx.x * blockDim.x + threadIdx.x) >> 5;
    if (w * 4 >= NN) return;
    int lane = threadIdx.x & 31;
    int q = lane >> 3, m = lane & 7;
    int n = 4 * w + q;                       // NN % 4 == 0 -> always valid
    int myh = m >> 1;
    float ad = g_ald1[n * 4 + myh];
    float ax[8];
    #pragma unroll
    for (int i = 0; i < 8; i++) ax[i] = 0.f;
    float z = 0.f;
    {   // self loop (each lane adds once; z is per-head, replicated in-lane)
        float w0 = lrelu_exp(g_als1[n * 4 + myh] + ad);
        z += w0;
        uint4 u = *(const uint4*)&g_h1h[(size_t)n * HD + m * 8];
        float2 p0 = __half22float2(*(__half2*)&u.x);
        float2 p1 = __half22float2(*(__half2*)&u.y);
        float2 p2 = __half22float2(*(__half2*)&u.z);
        float2 p3 = __half22float2(*(__half2*)&u.w);
        ax[0] += p0.x*w0; ax[1] += p0.y*w0; ax[2] += p1.x*w0; ax[3] += p1.y*w0;
        ax[4] += p2.x*w0; ax[5] += p2.y*w0; ax[6] += p3.x*w0; ax[7] += p3.y*w0;
    }
    int e = g_indptr[n], end = g_indptr[n + 1];
    for (; e + 4 <= end; e += 4) {
        int s0 = g_indices[e],     s1 = g_indices[e + 1];
        int s2 = g_indices[e + 2], s3 = g_indices[e + 3];
        float l0 = g_als1[s0 * 4 + myh], l1 = g_als1[s1 * 4 + myh];
        float l2 = g_als1[s2 * 4 + myh], l3 = g_als1[s3 * 4 + myh];
        uint4 u0 = *(const uint4*)&g_h1h[(size_t)s0 * HD + m * 8];
        uint4 u1 = *(const uint4*)&g_h1h[(size_t)s1 * HD + m * 8];
        uint4 u2 = *(const uint4*)&g_h1h[(size_t)s2 * HD + m * 8];
        uint4 u3 = *(const uint4*)&g_h1h[(size_t)s3 * HD + m * 8];
        float w0 = lrelu_exp(l0 + ad), w1 = lrelu_exp(l1 + ad);
        float w2 = lrelu_exp(l2 + ad), w3 = lrelu_exp(l3 + ad);
        z += (w0 + w1) + (w2 + w3);
        float2 q0 = __half22float2(*(__half2*)&u0.x), q1 = __half22float2(*(__half2*)&u0.y);
        float2 q2 = __half22float2(*(__half2*)&u0.z), q3 = __half22float2(*(__half2*)&u0.w);
        float2 r0 = __half22float2(*(__half2*)&u1.x), r1 = __half22float2(*(__half2*)&u1.y);
        float2 r2 = __half22float2(*(__half2*)&u1.z), r3 = __half22float2(*(__half2*)&u1.w);
        float2 t0 = __half22float2(*(__half2*)&u2.x), t1 = __half22float2(*(__half2*)&u2.y);
        float2 t2 = __half22float2(*(__half2*)&u2.z), t3 = __half22float2(*(__half2*)&u2.w);
        float2 v0 = __half22float2(*(__half2*)&u3.x), v1 = __half22float2(*(__half2*)&u3.y);
        float2 v2 = __half22float2(*(__half2*)&u3.z), v3 = __half22float2(*(__half2*)&u3.w);
        ax[0] += q0.x*w0 + r0.x*w1 + t0.x*w2 + v0.x*w3;
        ax[1] += q0.y*w0 + r0.y*w1 + t0.y*w2 + v0.y*w3;
        ax[2] += q1.x*w0 + r1.x*w1 + t1.x*w2 + v1.x*w3;
        ax[3] += q1.y*w0 + r1.y*w1 + t1.y*w2 + v1.y*w3;
        ax[4] += q2.x*w0 + r2.x*w1 + t2.x*w2 + v2.x*w3;
        ax[5] += q2.y*w0 + r2.y*w1 + t2.y*w2 + v2.y*w3;
        ax[6] += q3.x*w0 + r3.x*w1 + t3.x*w2 + v3.x*w3;
        ax[7] += q3.y*w0 + r3.y*w1 + t3.y*w2 + v3.y*w3;
    }
    for (; e < end; e++) {
        int s = g_indices[e];
        float l = g_als1[s * 4 + myh];
        uint4 u = *(const uint4*)&g_h1h[(size_t)s * HD + m * 8];
        float w0 = lrelu_exp(l + ad);
        z += w0;
        float2 p0 = __half22float2(*(__half2*)&u.x);
        float2 p1 = __half22float2(*(__half2*)&u.y);
        float2 p2 = __half22float2(*(__half2*)&u.z);
        float2 p3 = __half22float2(*(__half2*)&u.w);
        ax[0] += p0.x*w0; ax[1] += p0.y*w0; ax[2] += p1.x*w0; ax[3] += p1.y*w0;
        ax[4] += p2.x*w0; ax[5] += p2.y*w0; ax[6] += p3.x*w0; ax[7] += p3.y*w0;
    }
    __syncwarp();                            // re-converge before shfl epilogue
    float zi = 1.f / (z + 1e-16f);
    float4 bb0 = *(const float4*)&b1[m * 8];
    float4 bb1 = *(const float4*)&b1[m * 8 + 4];
    float f[8];
    f[0] = ax[0]*zi + bb0.x; f[1] = ax[1]*zi + bb0.y;
    f[2] = ax[2]*zi + bb0.z; f[3] = ax[3]*zi + bb0.w;
    f[4] = ax[4]*zi + bb1.x; f[5] = ax[5]*zi + bb1.y;
    f[6] = ax[6]*zi + bb1.z; f[7] = ax[7]*zi + bb1.w;
    #pragma unroll
    for (int i = 0; i < 8; i++) f[i] = f[i] > 0.f ? f[i] : expm1f(f[i]);  // ELU
    // ---- fused GEMV: lane computes output channels m*4..m*4+3 -------------
    float t0 = 0.f, t1 = 0.f, t2 = 0.f, t3 = 0.f;
    int qb = lane & 24;   // quarter base for shfl source
    #pragma unroll
    for (int k = 0; k < 8; k++) {
        #pragma unroll
        for (int j = 0; j < 8; j++) {
            float g = __shfl_sync(FULLM, f[j], qb + k);   // feat channel 8k+j of my node
            float4 wv = __ldg(&((const float4*)W2)[(8 * k + j) * 8 + m]);
            t0 += g * wv.x; t1 += g * wv.y; t2 += g * wv.z; t3 += g * wv.w;
        }
    }
    __half2 tp0 = __floats2half2_rn(t0, t1);
    __half2 tp1 = __floats2half2_rn(t2, t3);
    *(uint2*)&g_t2h[(size_t)n * DOUT + m * 4] = make_uint2(*(unsigned*)&tp0, *(unsigned*)&tp1);
    // ---- fused als2/ald2 (fp32 exact), reduce within quarter --------------
    float4 s2 = __ldg(&((const float4*)a_src2)[m]);
    float4 d2 = __ldg(&((const float4*)a_dst2)[m]);
    float ps = t0*s2.x + t1*s2.y + t2*s2.z + t3*s2.w;
    float pd = t0*d2.x + t1*d2.y + t2*d2.z + t3*d2.w;
    #pragma unroll
    for (int off = 1; off < 8; off <<= 1) {
        ps += __shfl_xor_sync(FULLM, ps, off);
        pd += __shfl_xor_sync(FULLM, pd, off);
    }
    if (m == 0) { g_als2[n] = ps; g_ald2[n] = pd; }
}

// ---------------- gather2: 4 nodes/warp, writes d_out ----------------------
// q = lane>>3 selects node; m = lane&7 owns channels 4m..4m+3 (uint2).
__global__ void gather2_kernel(float* __restrict__ out, const float* __restrict__ b2) {
    int w = (blockIdx.x * blockDim.x + threadIdx.x) >> 5;
    if (w * 4 >= NN) return;
    int lane = threadIdx.x & 31;
    int q = lane >> 3, m = lane & 7;
    int n = 4 * w + q;
    float ad = g_ald2[n];
    float a0 = 0.f, a1 = 0.f, a2 = 0.f, a3 = 0.f, z = 0.f;
    {   // self loop
        float w0 = lrelu_exp(g_als2[n] + ad);
        z += w0;
        uint2 u = *(const uint2*)&g_t2h[(size_t)n * DOUT + m * 4];
        float2 p0 = __half22float2(*(__half2*)&u.x);
        float2 p1 = __half22float2(*(__half2*)&u.y);
        a0 += p0.x*w0; a1 += p0.y*w0; a2 += p1.x*w0; a3 += p1.y*w0;
    }
    int e = g_indptr[n], end = g_indptr[n + 1];
    for (; e + 4 <= end; e += 4) {
        int s0 = g_indices[e],     s1 = g_indices[e + 1];
        int s2 = g_indices[e + 2], s3 = g_indices[e + 3];
        float l0 = g_als2[s0], l1 = g_als2[s1], l2 = g_als2[s2], l3 = g_als2[s3];
        uint2 u0 = *(const uint2*)&g_t2h[(size_t)s0 * DOUT + m * 4];
        uint2 u1 = *(const uint2*)&g_t2h[(size_t)s1 * DOUT + m * 4];
        uint2 u2 = *(const uint2*)&g_t2h[(size_t)s2 * DOUT + m * 4];
        uint2 u3 = *(const uint2*)&g_t2h[(size_t)s3 * DOUT + m * 4];
        float w0 = lrelu_exp(l0 + ad), w1 = lrelu_exp(l1 + ad);
        float w2 = lrelu_exp(l2 + ad), w3 = lrelu_exp(l3 + ad);
        z += (w0 + w1) + (w2 + w3);
        float2 q0 = __half22float2(*(__half2*)&u0.x), q1 = __half22float2(*(__half2*)&u0.y);
        float2 r0 = __half22float2(*(__half2*)&u1.x), r1 = __half22float2(*(__half2*)&u1.y);
        float2 t0 = __half22float2(*(__half2*)&u2.x), t1 = __half22float2(*(__half2*)&u2.y);
        float2 v0 = __half22float2(*(__half2*)&u3.x), v1 = __half22float2(*(__half2*)&u3.y);
        a0 += q0.x*w0 + r0.x*w1 + t0.x*w2 + v0.x*w3;
        a1 += q0.y*w0 + r0.y*w1 + t0.y*w2 + v0.y*w3;
        a2 += q1.x*w0 + r1.x*w1 + t1.x*w2 + v1.x*w3;
        a3 += q1.y*w0 + r1.y*w1 + t1.y*w2 + v1.y*w3;
    }
    for (; e < end; e++) {
        int s = g_indices[e];
        float l = g_als2[s];
        uint2 u = *(const uint2*)&g_t2h[(size_t)s * DOUT + m * 4];
        float w0 = lrelu_exp(l + ad);
        z += w0;
        float2 p0 = __half22float2(*(__half2*)&u.x);
        float2 p1 = __half22float2(*(__half2*)&u.y);
        a0 += p0.x*w0; a1 += p0.y*w0; a2 += p1.x*w0; a3 += p1.y*w0;
    }
    float zi = 1.f / (z + 1e-16f);
    float4 bb = *(const float4*)&b2[m * 4];
    *(float4*)&out[(size_t)n * DOUT + m * 4] =
        make_float4(a0 * zi + bb.x, a1 * zi + bb.y, a2 * zi + bb.z, a3 * zi + bb.w);
}

// ---------------------------------------------------------------------------
extern "C" void kernel_launch(void* const* d_in, const int* in_sizes, int n_in,
                              void* d_out, int out_size) {
    const float*     x      = (const float*)d_in[0];
    const long long* ei     = (const long long*)d_in[1];
    const float*     W1     = (const float*)d_in[2];
    const float*     a_src1 = (const float*)d_in[3];
    const float*     a_dst1 = (const float*)d_in[4];
    const float*     b1     = (const float*)d_in[5];
    const float*     W2     = (const float*)d_in[6];
    const float*     a_src2 = (const float*)d_in[7];
    const float*     a_dst2 = (const float*)d_in[8];
    const float*     b2     = (const float*)d_in[9];
    float* out = (float*)d_out;

    const int NB = (NN + 255) / 256;
    const int GB = (NN + 127) / 128;
    const int E2 = (EE / 2 + 255) / 256;
    const int WB = ((NN / 4) * 32 + 255) / 256;   // 4 nodes per warp

    // zero degree counters via memset node (not a kernel launch)
    void* cntPtr = nullptr;
    cudaGetSymbolAddress(&cntPtr, g_cnt);
    cudaMemsetAsync(cntPtr, 0, NN * sizeof(int), 0);

    cudaEventRecord(g_evFork, 0);
    cudaStreamWaitEvent(g_s2, g_evFork, 0);

    detect_kernel<<<1, 32>>>(ei);
    convert_count_kernel<<<E2, 256>>>(ei);
    scan1_kernel<<<NBLK, 1024>>>();
    gemm1_kernel<<<GB, 256, G1_SMEM, g_s2>>>(x, W1, a_src1, a_dst1);
    cudaEventRecord(g_evJoin, g_s2);
    scan23_kernel<<<NB, 256>>>();
    scatter_kernel<<<E2, 256>>>();

    cudaStreamWaitEvent(0, g_evJoin, 0);
    gather1_fused_kernel<<<WB, 256>>>(b1, W2, a_src2, a_dst2);
    gather2_kernel<<<WB, 256>>>(out, b2);
}

// round 15
// speedup vs baseline: 1.2972x; 1.0275x over previous
#include <cuda_runtime.h>
#include <cuda_fp16.h>
#include <math.h>

#define NN   100000
#define EE   1600000
#define DIN  128
#define HD   64      // HEADS*HID
#define HEADS 4
#define HID  16
#define DOUT 32
#define NEG  0.2f
#define NBLK ((NN + 1023) / 1024)   // scan blocks = 98
#define KC   32                      // k-chunk
#define XS_STRIDE 36
#define G1_SMEM ((DIN * HD + 128 * XS_STRIDE) * 4)   // 51200 B
#define FULLM 0xffffffffu

typedef unsigned long long u64;

// ---------------- scratch (device globals; no allocation allowed) ----------
__device__ __align__(16) __half g_h1h[NN * HD];     // x @ W1   (fp16 storage)
__device__ __align__(16) float g_als1[NN * HEADS];
__device__ __align__(16) float g_ald1[NN * HEADS];
__device__ __align__(16) __half g_t2h[NN * DOUT];   // feat1 @ W2 (fp16 storage)
__device__ __align__(16) float g_als2[NN];
__device__ __align__(16) float g_ald2[NN];
// CSR scratch
__device__ __align__(16) int g_rank[EE];            // per-dst arrival rank
__device__ int g_cnt[NN];
__device__ int g_indptr[NN + 1];                    // block-local exclusive scan
__device__ int g_boff[NBLK];                        // per-block offsets
__device__ int g_indices[EE];
__device__ int g_bsum[NBLK];
__device__ int g_is64;

__global__ void gemm1_kernel(const float*, const float*, const float*, const float*);

// ---------------- stream/event for fork-join overlap (created pre-main) ----
static cudaStream_t g_s2;
static cudaEvent_t g_evFork, g_evJoin;
static struct Boot {
    Boot() {
        cudaStreamCreateWithFlags(&g_s2, cudaStreamNonBlocking);
        cudaEventCreateWithFlags(&g_evFork, cudaEventDisableTiming);
        cudaEventCreateWithFlags(&g_evJoin, cudaEventDisableTiming);
        cudaFuncSetAttribute(gemm1_kernel,
                             cudaFuncAttributeMaxDynamicSharedMemorySize, G1_SMEM);
    }
} g_boot;

__device__ __forceinline__ float lrelu_exp(float l) {
    l = fmaxf(l, NEG * l);                // branchless leaky relu
    return __expf(fminf(l, 25.f));        // clamp is a no-op safety net
}

// ---- packed fp32x2 helpers (sm_103a FFMA2 path; exact fp32 rounding) ------
__device__ __forceinline__ u64 packf2(float a, float b) {
    u64 r; asm("mov.b64 %0, {%1, %2};" : "=l"(r) : "f"(a), "f"(b)); return r;
}
__device__ __forceinline__ void ffma2(u64& d, u64 a, u64 b) {
    asm("fma.rn.f32x2 %0, %1, %2, %0;" : "+l"(d) : "l"(a), "l"(b));
}
__device__ __forceinline__ float2 unpackf2(u64 v) {
    float2 r; asm("mov.b64 {%0, %1}, %2;" : "=f"(r.x), "=f"(r.y) : "l"(v)); return r;
}

// ---------------- detect dtype (1 warp) ------------------------------------
__global__ void detect_kernel(const long long* ei) {
    if (threadIdx.x == 0) {
        int ok = 1;
        for (int k = 0; k < 64; k++) {
            long long v = ei[k];
            if (v < 0 || v >= NN) { ok = 0; break; }
        }
        g_is64 = ok;
    }
}

// ---------------- count + rank (2 edges/thread; no src/dst mirror) ---------
__global__ void convert_count_kernel(const long long* __restrict__ ei) {
    int e = (blockIdx.x * blockDim.x + threadIdx.x) * 2;
    if (e >= EE) return;
    int d0, d1;
    if (g_is64) {
        longlong2 dv = *(const longlong2*)&ei[e + EE];
        d0 = (int)dv.x; d1 = (int)dv.y;
    } else {
        const int* p = (const int*)ei;
        int2 dv = *(const int2*)&p[e + EE];
        d0 = dv.x; d1 = dv.y;
    }
    int r0 = atomicAdd(&g_cnt[d0], 1);
    int r1 = atomicAdd(&g_cnt[d1], 1);
    *(int2*)&g_rank[e] = make_int2(r0, r1);
}

// ---------------- scan phase 1: per-block exclusive scan -------------------
__global__ void scan1_kernel() {
    __shared__ int wsum[32];
    int t = threadIdx.x;
    int i = blockIdx.x * 1024 + t;
    int v = (i < NN) ? g_cnt[i] : 0;
    int lane = t & 31, wid = t >> 5;
    int p = v;
    #pragma unroll
    for (int off = 1; off < 32; off <<= 1) {
        int a = __shfl_up_sync(FULLM, p, off);
        if (lane >= off) p += a;
    }
    if (lane == 31) wsum[wid] = p;
    __syncthreads();
    if (wid == 0) {
        int s = wsum[lane];
        #pragma unroll
        for (int off = 1; off < 32; off <<= 1) {
            int a = __shfl_up_sync(FULLM, s, off);
            if (lane >= off) s += a;
        }
        wsum[lane] = s;
    }
    __syncthreads();
    int base = (wid > 0) ? wsum[wid - 1] : 0;
    int incl = p + base;
    if (i < NN) g_indptr[i] = incl - v;      // exclusive within block
    if (t == 1023) g_bsum[blockIdx.x] = incl;
}

// ---------------- scan phase 2: block offsets (1 block) --------------------
__global__ void scan2_kernel() {
    __shared__ int sh[128];
    int t = threadIdx.x;
    int v = (t < NBLK) ? g_bsum[t] : 0;
    sh[t] = v;
    __syncthreads();
    #pragma unroll
    for (int off = 1; off < 128; off <<= 1) {
        int a = (t >= off) ? sh[t - off] : 0;
        __syncthreads();
        sh[t] += a;
        __syncthreads();
    }
    if (t < NBLK) g_boff[t] = sh[t] - v;     // exclusive
    // make indptr[NN] + boff[NN>>10] == EE  (NN>>10 == NBLK-1)
    if (t == NBLK - 1) g_indptr[NN] = EE - (sh[t] - v);
}

// ---------------- CSR scatter: reads ei (L2-hot) + rank, boff inline -------
__global__ void scatter_kernel(const long long* __restrict__ ei) {
    int e = (blockIdx.x * blockDim.x + threadIdx.x) * 2;
    if (e >= EE) return;
    int s0, s1, d0, d1;
    if (g_is64) {
        longlong2 sv = *(const longlong2*)&ei[e];
        longlong2 dv = *(const longlong2*)&ei[e + EE];
        s0 = (int)sv.x; s1 = (int)sv.y; d0 = (int)dv.x; d1 = (int)dv.y;
    } else {
        const int* p = (const int*)ei;
        int2 sv = *(const int2*)&p[e];
        int2 dv = *(const int2*)&p[e + EE];
        s0 = sv.x; s1 = sv.y; d0 = dv.x; d1 = dv.y;
    }
    int2 r = *(const int2*)&g_rank[e];
    g_indices[g_indptr[d0] + g_boff[d0 >> 10] + r.x] = s0;
    g_indices[g_indptr[d1] + g_boff[d1 >> 10] + r.y] = s1;
}

// ---------------- GEMM1 (smem W, chunked xs, packed FFMA2) + als1/ald1 -----
__global__ __launch_bounds__(256, 4)
void gemm1_kernel(const float* __restrict__ x, const float* __restrict__ W,
                  const float* __restrict__ a_src, const float* __restrict__ a_dst) {
    extern __shared__ float sm[];
    float* ws = sm;                         // [128][64]
    float* xs = sm + DIN * HD;              // [128][XS_STRIDE]
    int t = threadIdx.x;
    int bn = blockIdx.x * 128;
    for (int i = t; i < DIN * HD / 4; i += 256)
        ((float4*)ws)[i] = ((const float4*)W)[i];

    int colq = t & 7;
    int nr   = t >> 3;
    u64 accA[4][2], accB[4][2];
    #pragma unroll
    for (int i = 0; i < 4; i++) {
        accA[i][0] = accA[i][1] = 0ULL;
        accB[i][0] = accB[i][1] = 0ULL;
    }
    for (int kc = 0; kc < DIN; kc += KC) {
        __syncthreads();
        #pragma unroll
        for (int i = t; i < 128 * 8; i += 256) {
            int r = i >> 3, c = i & 7;
            int node = bn + r;
            float4 v = (node < NN)
                ? *(const float4*)&x[(size_t)node * DIN + kc + c * 4]
                : make_float4(0.f, 0.f, 0.f, 0.f);
            *(float4*)&xs[r * XS_STRIDE + c * 4] = v;
        }
        __syncthreads();
        #pragma unroll 8
        for (int kk = 0; kk < KC; kk++) {
            ulonglong2 wa = *(const ulonglong2*)&ws[(kc + kk) * HD + colq * 4];
            ulonglong2 wb = *(const ulonglong2*)&ws[(kc + kk) * HD + 32 + colq * 4];
            float x0 = xs[nr * XS_STRIDE + kk];
            float x1 = xs[(nr + 32) * XS_STRIDE + kk];
            float x2 = xs[(nr + 64) * XS_STRIDE + kk];
            float x3 = xs[(nr + 96) * XS_STRIDE + kk];
            u64 X0 = packf2(x0, x0), X1 = packf2(x1, x1);
            u64 X2 = packf2(x2, x2), X3 = packf2(x3, x3);
            ffma2(accA[0][0], X0, wa.x); ffma2(accA[0][1], X0, wa.y);
            ffma2(accB[0][0], X0, wb.x); ffma2(accB[0][1], X0, wb.y);
            ffma2(accA[1][0], X1, wa.x); ffma2(accA[1][1], X1, wa.y);
            ffma2(accB[1][0], X1, wb.x); ffma2(accB[1][1], X1, wb.y);
            ffma2(accA[2][0], X2, wa.x); ffma2(accA[2][1], X2, wa.y);
            ffma2(accB[2][0], X2, wb.x); ffma2(accB[2][1], X2, wb.y);
            ffma2(accA[3][0], X3, wa.x); ffma2(accA[3][1], X3, wa.y);
            ffma2(accB[3][0], X3, wb.x); ffma2(accB[3][1], X3, wb.y);
        }
    }
    int hA = colq >> 2;
    int hB = 2 + hA;
    int woff = (colq & 3) * 4;
    float4 sA = *(const float4*)&a_src[hA * HID + woff];
    float4 dA = *(const float4*)&a_dst[hA * HID + woff];
    float4 sB = *(const float4*)&a_src[hB * HID + woff];
    float4 dB = *(const float4*)&a_dst[hB * HID + woff];
    #pragma unroll
    for (int i = 0; i < 4; i++) {
        int node = bn + nr + i * 32;
        bool ok = node < NN;
        float2 a01 = unpackf2(accA[i][0]);
        float2 a23 = unpackf2(accA[i][1]);
        float2 b01 = unpackf2(accB[i][0]);
        float2 b23 = unpackf2(accB[i][1]);
        if (ok) {
            __half2 pa0 = __floats2half2_rn(a01.x, a01.y);
            __half2 pa1 = __floats2half2_rn(a23.x, a23.y);
            __half2 pb0 = __floats2half2_rn(b01.x, b01.y);
            __half2 pb1 = __floats2half2_rn(b23.x, b23.y);
            *(uint2*)&g_h1h[(size_t)node * HD + colq * 4]      = make_uint2(*(unsigned*)&pa0, *(unsigned*)&pa1);
            *(uint2*)&g_h1h[(size_t)node * HD + 32 + colq * 4] = make_uint2(*(unsigned*)&pb0, *(unsigned*)&pb1);
        }
        float psA = a01.x*sA.x + a01.y*sA.y + a23.x*sA.z + a23.y*sA.w;
        float pdA = a01.x*dA.x + a01.y*dA.y + a23.x*dA.z + a23.y*dA.w;
        float psB = b01.x*sB.x + b01.y*sB.y + b23.x*sB.z + b23.y*sB.w;
        float pdB = b01.x*dB.x + b01.y*dB.y + b23.x*dB.z + b23.y*dB.w;
        #pragma unroll
        for (int off = 1; off < 4; off <<= 1) {
            psA += __shfl_xor_sync(FULLM, psA, off);
            pdA += __shfl_xor_sync(FULLM, pdA, off);
            psB += __shfl_xor_sync(FULLM, psB, off);
            pdB += __shfl_xor_sync(FULLM, pdB, off);
        }
        if (((colq & 3) == 0) && ok) {
            g_als1[node * 4 + hA] = psA;
            g_ald1[node * 4 + hA] = pdA;
            g_als1[node * 4 + hB] = psB;
            g_ald1[node * 4 + hB] = pdB;
        }
    }
}

// ---------------- FUSED gather1: 4 nodes/warp (8-lane quarter per node) ----
__global__ void gather1_fused_kernel(const float* __restrict__ b1,
                                     const float* __restrict__ W2,
                                     const float* __restrict__ a_src2,
                                     const float* __restrict__ a_dst2) {
    int w = (blockIdx.x * blockDim.x + threadIdx.x) >> 5;
    if (w * 4 >= NN) return;
    int lane = threadIdx.x & 31;
    int q = lane >> 3, m = lane & 7;
    int n = 4 * w + q;                       // NN % 4 == 0 -> always valid
    int myh = m >> 1;
    float ad = g_ald1[n * 4 + myh];
    float ax[8];
    #pragma unroll
    for (int i = 0; i < 8; i++) ax[i] = 0.f;
    float z = 0.f;
    {   // self loop
        float w0 = lrelu_exp(g_als1[n * 4 + myh] + ad);
        z += w0;
        uint4 u = *(const uint4*)&g_h1h[(size_t)n * HD + m * 8];
        float2 p0 = __half22float2(*(__half2*)&u.x);
        float2 p1 = __half22float2(*(__half2*)&u.y);
        float2 p2 = __half22float2(*(__half2*)&u.z);
        float2 p3 = __half22float2(*(__half2*)&u.w);
        ax[0] += p0.x*w0; ax[1] += p0.y*w0; ax[2] += p1.x*w0; ax[3] += p1.y*w0;
        ax[4] += p2.x*w0; ax[5] += p2.y*w0; ax[6] += p3.x*w0; ax[7] += p3.y*w0;
    }
    int e   = g_indptr[n]     + g_boff[n >> 10];
    int end = g_indptr[n + 1] + g_boff[(n + 1) >> 10];
    for (; e + 4 <= end; e += 4) {
        int s0 = g_indices[e],     s1 = g_indices[e + 1];
        int s2 = g_indices[e + 2], s3 = g_indices[e + 3];
        float l0 = g_als1[s0 * 4 + myh], l1 = g_als1[s1 * 4 + myh];
        float l2 = g_als1[s2 * 4 + myh], l3 = g_als1[s3 * 4 + myh];
        uint4 u0 = *(const uint4*)&g_h1h[(size_t)s0 * HD + m * 8];
        uint4 u1 = *(const uint4*)&g_h1h[(size_t)s1 * HD + m * 8];
        uint4 u2 = *(const uint4*)&g_h1h[(size_t)s2 * HD + m * 8];
        uint4 u3 = *(const uint4*)&g_h1h[(size_t)s3 * HD + m * 8];
        float w0 = lrelu_exp(l0 + ad), w1 = lrelu_exp(l1 + ad);
        float w2 = lrelu_exp(l2 + ad), w3 = lrelu_exp(l3 + ad);
        z += (w0 + w1) + (w2 + w3);
        float2 q0 = __half22float2(*(__half2*)&u0.x), q1 = __half22float2(*(__half2*)&u0.y);
        float2 q2 = __half22float2(*(__half2*)&u0.z), q3 = __half22float2(*(__half2*)&u0.w);
        float2 r0 = __half22float2(*(__half2*)&u1.x), r1 = __half22float2(*(__half2*)&u1.y);
        float2 r2 = __half22float2(*(__half2*)&u1.z), r3 = __half22float2(*(__half2*)&u1.w);
        float2 t0 = __half22float2(*(__half2*)&u2.x), t1 = __half22float2(*(__half2*)&u2.y);
        float2 t2 = __half22float2(*(__half2*)&u2.z), t3 = __half22float2(*(__half2*)&u2.w);
        float2 v0 = __half22float2(*(__half2*)&u3.x), v1 = __half22float2(*(__half2*)&u3.y);
        float2 v2 = __half22float2(*(__half2*)&u3.z), v3 = __half22float2(*(__half2*)&u3.w);
        ax[0] += q0.x*w0 + r0.x*w1 + t0.x*w2 + v0.x*w3;
        ax[1] += q0.y*w0 + r0.y*w1 + t0.y*w2 + v0.y*w3;
        ax[2] += q1.x*w0 + r1.x*w1 + t1.x*w2 + v1.x*w3;
        ax[3] += q1.y*w0 + r1.y*w1 + t1.y*w2 + v1.y*w3;
        ax[4] += q2.x*w0 + r2.x*w1 + t2.x*w2 + v2.x*w3;
        ax[5] += q2.y*w0 + r2.y*w1 + t2.y*w2 + v2.y*w3;
        ax[6] += q3.x*w0 + r3.x*w1 + t3.x*w2 + v3.x*w3;
        ax[7] += q3.y*w0 + r3.y*w1 + t3.y*w2 + v3.y*w3;
    }
    for (; e < end; e++) {
        int s = g_indices[e];
        float l = g_als1[s * 4 + myh];
        uint4 u = *(const uint4*)&g_h1h[(size_t)s * HD + m * 8];
        float w0 = lrelu_exp(l + ad);
        z += w0;
        float2 p0 = __half22float2(*(__half2*)&u.x);
        float2 p1 = __half22float2(*(__half2*)&u.y);
        float2 p2 = __half22float2(*(__half2*)&u.z);
        float2 p3 = __half22float2(*(__half2*)&u.w);
        ax[0] += p0.x*w0; ax[1] += p0.y*w0; ax[2] += p1.x*w0; ax[3] += p1.y*w0;
        ax[4] += p2.x*w0; ax[5] += p2.y*w0; ax[6] += p3.x*w0; ax[7] += p3.y*w0;
    }
    __syncwarp();                            // re-converge before shfl epilogue
    float zi = 1.f / (z + 1e-16f);
    float4 bb0 = *(const float4*)&b1[m * 8];
    float4 bb1 = *(const float4*)&b1[m * 8 + 4];
    float f[8];
    f[0] = ax[0]*zi + bb0.x; f[1] = ax[1]*zi + bb0.y;
    f[2] = ax[2]*zi + bb0.z; f[3] = ax[3]*zi + bb0.w;
    f[4] = ax[4]*zi + bb1.x; f[5] = ax[5]*zi + bb1.y;
    f[6] = ax[6]*zi + bb1.z; f[7] = ax[7]*zi + bb1.w;
    #pragma unroll
    for (int i = 0; i < 8; i++) f[i] = f[i] > 0.f ? f[i] : expm1f(f[i]);  // ELU
    // ---- fused GEMV: lane computes output channels m*4..m*4+3 -------------
    float t0 = 0.f, t1 = 0.f, t2 = 0.f, t3 = 0.f;
    int qb = lane & 24;   // quarter base for shfl source
    #pragma unroll
    for (int k = 0; k < 8; k++) {
        #pragma unroll
        for (int j = 0; j < 8; j++) {
            float g = __shfl_sync(FULLM, f[j], qb + k);   // feat channel 8k+j of my node
            float4 wv = __ldg(&((const float4*)W2)[(8 * k + j) * 8 + m]);
            t0 += g * wv.x; t1 += g * wv.y; t2 += g * wv.z; t3 += g * wv.w;
        }
    }
    __half2 tp0 = __floats2half2_rn(t0, t1);
    __half2 tp1 = __floats2half2_rn(t2, t3);
    *(uint2*)&g_t2h[(size_t)n * DOUT + m * 4] = make_uint2(*(unsigned*)&tp0, *(unsigned*)&tp1);
    // ---- fused als2/ald2 (fp32 exact), reduce within quarter --------------
    float4 s2 = __ldg(&((const float4*)a_src2)[m]);
    float4 d2 = __ldg(&((const float4*)a_dst2)[m]);
    float ps = t0*s2.x + t1*s2.y + t2*s2.z + t3*s2.w;
    float pd = t0*d2.x + t1*d2.y + t2*d2.z + t3*d2.w;
    #pragma unroll
    for (int off = 1; off < 8; off <<= 1) {
        ps += __shfl_xor_sync(FULLM, ps, off);
        pd += __shfl_xor_sync(FULLM, pd, off);
    }
    if (m == 0) { g_als2[n] = ps; g_ald2[n] = pd; }
}

// ---------------- gather2: 8 nodes/warp (4-lane group per node) ------------
// g = lane>>2 selects node 8w+g; ml = lane&3 owns channels 8ml..8ml+7 (uint4).
// z and weights replicated within the group -> no reductions, direct stores.
__global__ void gather2_kernel(float* __restrict__ out, const float* __restrict__ b2) {
    int w = (blockIdx.x * blockDim.x + threadIdx.x) >> 5;
    if (w * 8 >= NN) return;
    int lane = threadIdx.x & 31;
    int g = lane >> 2, ml = lane & 3;
    int n = 8 * w + g;                       // NN % 8 == 0 -> always valid
    float ad = g_ald2[n];
    float a0 = 0.f, a1 = 0.f, a2 = 0.f, a3 = 0.f;
    float a4 = 0.f, a5 = 0.f, a6 = 0.f, a7 = 0.f, z = 0.f;
    {   // self loop
        float w0 = lrelu_exp(g_als2[n] + ad);
        z += w0;
        uint4 u = *(const uint4*)&g_t2h[(size_t)n * DOUT + ml * 8];
        float2 p0 = __half22float2(*(__half2*)&u.x);
        float2 p1 = __half22float2(*(__half2*)&u.y);
        float2 p2 = __half22float2(*(__half2*)&u.z);
        float2 p3 = __half22float2(*(__half2*)&u.w);
        a0 += p0.x*w0; a1 += p0.y*w0; a2 += p1.x*w0; a3 += p1.y*w0;
        a4 += p2.x*w0; a5 += p2.y*w0; a6 += p3.x*w0; a7 += p3.y*w0;
    }
    int e   = g_indptr[n]     + g_boff[n >> 10];
    int end = g_indptr[n + 1] + g_boff[(n + 1) >> 10];
    for (; e + 4 <= end; e += 4) {
        int s0 = g_indices[e],     s1 = g_indices[e + 1];
        int s2 = g_indices[e + 2], s3 = g_indices[e + 3];
        float l0 = g_als2[s0], l1 = g_als2[s1], l2 = g_als2[s2], l3 = g_als2[s3];
        uint4 u0 = *(const uint4*)&g_t2h[(size_t)s0 * DOUT + ml * 8];
        uint4 u1 = *(const uint4*)&g_t2h[(size_t)s1 * DOUT + ml * 8];
        uint4 u2 = *(const uint4*)&g_t2h[(size_t)s2 * DOUT + ml * 8];
        uint4 u3 = *(const uint4*)&g_t2h[(size_t)s3 * DOUT + ml * 8];
        float w0 = lrelu_exp(l0 + ad), w1 = lrelu_exp(l1 + ad);
        float w2 = lrelu_exp(l2 + ad), w3 = lrelu_exp(l3 + ad);
        z += (w0 + w1) + (w2 + w3);
        float2 q0 = __half22float2(*(__half2*)&u0.x), q1 = __half22float2(*(__half2*)&u0.y);
        float2 q2 = __half22float2(*(__half2*)&u0.z), q3 = __half22float2(*(__half2*)&u0.w);
        float2 r0 = __half22float2(*(__half2*)&u1.x), r1 = __half22float2(*(__half2*)&u1.y);
        float2 r2 = __half22float2(*(__half2*)&u1.z), r3 = __half22float2(*(__half2*)&u1.w);
        float2 t0 = __half22float2(*(__half2*)&u2.x), t1 = __half22float2(*(__half2*)&u2.y);
        float2 t2 = __half22float2(*(__half2*)&u2.z), t3 = __half22float2(*(__half2*)&u2.w);
        float2 v0 = __half22float2(*(__half2*)&u3.x), v1 = __half22float2(*(__half2*)&u3.y);
        float2 v2 = __half22float2(*(__half2*)&u3.z), v3 = __half22float2(*(__half2*)&u3.w);
        a0 += q0.x*w0 + r0.x*w1 + t0.x*w2 + v0.x*w3;
        a1 += q0.y*w0 + r0.y*w1 + t0.y*w2 + v0.y*w3;
        a2 += q1.x*w0 + r1.x*w1 + t1.x*w2 + v1.x*w3;
        a3 += q1.y*w0 + r1.y*w1 + t1.y*w2 + v1.y*w3;
        a4 += q2.x*w0 + r2.x*w1 + t2.x*w2 + v2.x*w3;
        a5 += q2.y*w0 + r2.y*w1 + t2.y*w2 + v2.y*w3;
        a6 += q3.x*w0 + r3.x*w1 + t3.x*w2 + v3.x*w3;
        a7 += q3.y*w0 + r3.y*w1 + t3.y*w2 + v3.y*w3;
    }
    for (; e < end; e++) {
        int s = g_indices[e];
        float l = g_als2[s];
        uint4 u = *(const uint4*)&g_t2h[(size_t)s * DOUT + ml * 8];
        float w0 = lrelu_exp(l + ad);
        z += w0;
        float2 p0 = __half22float2(*(__half2*)&u.x);
        float2 p1 = __half22float2(*(__half2*)&u.y);
        float2 p2 = __half22float2(*(__half2*)&u.z);
        float2 p3 = __half22float2(*(__half2*)&u.w);
        a0 += p0.x*w0; a1 += p0.y*w0; a2 += p1.x*w0; a3 += p1.y*w0;
        a4 += p2.x*w0; a5 += p2.y*w0; a6 += p3.x*w0; a7 += p3.y*w0;
    }
    float zi = 1.f / (z + 1e-16f);
    float4 bb0 = *(const float4*)&b2[ml * 8];
    float4 bb1 = *(const float4*)&b2[ml * 8 + 4];
    float* op = &out[(size_t)n * DOUT + ml * 8];
    *(float4*)op       = make_float4(a0 * zi + bb0.x, a1 * zi + bb0.y,
                                     a2 * zi + bb0.z, a3 * zi + bb0.w);
    *(float4*)(op + 4) = make_float4(a4 * zi + bb1.x, a5 * zi + bb1.y,
                                     a6 * zi + bb1.z, a7 * zi + bb1.w);
}

// ---------------------------------------------------------------------------
extern "C" void kernel_launch(void* const* d_in, const int* in_sizes, int n_in,
                              void* d_out, int out_size) {
    const float*     x      = (const float*)d_in[0];
    const long long* ei     = (const long long*)d_in[1];
    const float*     W1     = (const float*)d_in[2];
    const float*     a_src1 = (const float*)d_in[3];
    const float*     a_dst1 = (const float*)d_in[4];
    const float*     b1     = (const float*)d_in[5];
    const float*     W2     = (const float*)d_in[6];
    const float*     a_src2 = (const float*)d_in[7];
    const float*     a_dst2 = (const float*)d_in[8];
    const float*     b2     = (const float*)d_in[9];
    float* out = (float*)d_out;

    const int GB  = (NN + 127) / 128;
    const int E2  = (EE / 2 + 255) / 256;
    const int WB1 = ((NN / 4) * 32 + 255) / 256;   // 4 nodes per warp
    const int WB2 = ((NN / 8) * 32 + 255) / 256;   // 8 nodes per warp

    // zero degree counters via memset node (not a kernel launch)
    void* cntPtr = nullptr;
    cudaGetSymbolAddress(&cntPtr, g_cnt);
    cudaMemsetAsync(cntPtr, 0, NN * sizeof(int), 0);

    cudaEventRecord(g_evFork, 0);
    cudaStreamWaitEvent(g_s2, g_evFork, 0);

    detect_kernel<<<1, 32>>>(ei);
    convert_count_kernel<<<E2, 256>>>(ei);
    scan1_kernel<<<NBLK, 1024>>>();
    gemm1_kernel<<<GB, 256, G1_SMEM, g_s2>>>(x, W1, a_src1, a_dst1);
    cudaEventRecord(g_evJoin, g_s2);
    scan2_kernel<<<1, 128>>>();
    scatter_kernel<<<E2, 256>>>(ei);

    cudaStreamWaitEvent(0, g_evJoin, 0);
    gather1_fused_kernel<<<WB1, 256>>>(b1, W2, a_src2, a_dst2);
    gather2_kernel<<<WB2, 256>>>(out, b2);
}

// round 16
// speedup vs baseline: 1.4383x; 1.1088x over previous
#include <cuda_runtime.h>
#include <cuda_fp16.h>
#include <math.h>

#define NN   100000
#define EE   1600000
#define DIN  128
#define HD   64      // HEADS*HID
#define HEADS 4
#define HID  16
#define DOUT 32
#define NEG  0.2f
#define NBLK ((NN + 1023) / 1024)   // scan blocks = 98
#define XA_STRIDE 136               // halves, padded
#define WB_STRIDE 72                // halves, padded
#define G1_SMEM ((128 * XA_STRIDE + DIN * WB_STRIDE) * 2)   // 53248 B
#define FULLM 0xffffffffu

typedef unsigned long long u64;

// ---------------- scratch (device globals; no allocation allowed) ----------
__device__ __align__(16) __half g_h1h[NN * HD];     // x @ W1   (fp16 storage)
__device__ __align__(16) float g_als1[NN * HEADS];
__device__ __align__(16) float g_ald1[NN * HEADS];
__device__ __align__(16) __half g_t2h[NN * DOUT];   // feat1 @ W2 (fp16 storage)
__device__ __align__(16) float g_als2[NN];
__device__ __align__(16) float g_ald2[NN];
// CSR scratch
__device__ __align__(16) int g_rank[EE];            // per-dst arrival rank
__device__ int g_cnt[NN];
__device__ int g_indptr[NN + 1];                    // block-local exclusive scan
__device__ int g_boff[NBLK];                        // per-block offsets
__device__ int g_indices[EE];
__device__ int g_bsum[NBLK];
__device__ int g_is64;

__global__ void gemm1_kernel(const float*, const float*, const float*, const float*);

// ---------------- stream/event for fork-join overlap (created pre-main) ----
static cudaStream_t g_s2;
static cudaEvent_t g_evFork, g_evJoin;
static struct Boot {
    Boot() {
        cudaStreamCreateWithFlags(&g_s2, cudaStreamNonBlocking);
        cudaEventCreateWithFlags(&g_evFork, cudaEventDisableTiming);
        cudaEventCreateWithFlags(&g_evJoin, cudaEventDisableTiming);
        cudaFuncSetAttribute(gemm1_kernel,
                             cudaFuncAttributeMaxDynamicSharedMemorySize, G1_SMEM);
    }
} g_boot;

__device__ __forceinline__ float lrelu_exp(float l) {
    l = fmaxf(l, NEG * l);                // branchless leaky relu
    return __expf(fminf(l, 25.f));        // clamp is a no-op safety net
}

// ---- tensor-core primitives ----------------------------------------------
__device__ __forceinline__ void ldsm_x4(unsigned& r0, unsigned& r1, unsigned& r2, unsigned& r3,
                                        unsigned addr) {
    asm volatile("ldmatrix.sync.aligned.m8n8.x4.shared.b16 {%0,%1,%2,%3}, [%4];"
                 : "=r"(r0), "=r"(r1), "=r"(r2), "=r"(r3) : "r"(addr));
}
__device__ __forceinline__ void ldsm_x2t(unsigned& r0, unsigned& r1, unsigned addr) {
    asm volatile("ldmatrix.sync.aligned.m8n8.x2.trans.shared.b16 {%0,%1}, [%2];"
                 : "=r"(r0), "=r"(r1) : "r"(addr));
}
__device__ __forceinline__ void mma16816(float* c,
        unsigned a0, unsigned a1, unsigned a2, unsigned a3,
        unsigned b0, unsigned b1) {
    asm volatile("mma.sync.aligned.m16n8k16.row.col.f32.f16.f16.f32 "
                 "{%0,%1,%2,%3}, {%4,%5,%6,%7}, {%8,%9}, {%0,%1,%2,%3};"
                 : "+f"(c[0]), "+f"(c[1]), "+f"(c[2]), "+f"(c[3])
                 : "r"(a0), "r"(a1), "r"(a2), "r"(a3), "r"(b0), "r"(b1));
}

// ---------------- detect dtype (1 warp) ------------------------------------
__global__ void detect_kernel(const long long* ei) {
    if (threadIdx.x == 0) {
        int ok = 1;
        for (int k = 0; k < 64; k++) {
            long long v = ei[k];
            if (v < 0 || v >= NN) { ok = 0; break; }
        }
        g_is64 = ok;
    }
}

// ---------------- count + rank (2 edges/thread) -----------------------------
__global__ void convert_count_kernel(const long long* __restrict__ ei) {
    int e = (blockIdx.x * blockDim.x + threadIdx.x) * 2;
    if (e >= EE) return;
    int d0, d1;
    if (g_is64) {
        longlong2 dv = *(const longlong2*)&ei[e + EE];
        d0 = (int)dv.x; d1 = (int)dv.y;
    } else {
        const int* p = (const int*)ei;
        int2 dv = *(const int2*)&p[e + EE];
        d0 = dv.x; d1 = dv.y;
    }
    int r0 = atomicAdd(&g_cnt[d0], 1);
    int r1 = atomicAdd(&g_cnt[d1], 1);
    *(int2*)&g_rank[e] = make_int2(r0, r1);
}

// ---------------- scan phase 1: per-block exclusive scan -------------------
__global__ void scan1_kernel() {
    __shared__ int wsum[32];
    int t = threadIdx.x;
    int i = blockIdx.x * 1024 + t;
    int v = (i < NN) ? g_cnt[i] : 0;
    int lane = t & 31, wid = t >> 5;
    int p = v;
    #pragma unroll
    for (int off = 1; off < 32; off <<= 1) {
        int a = __shfl_up_sync(FULLM, p, off);
        if (lane >= off) p += a;
    }
    if (lane == 31) wsum[wid] = p;
    __syncthreads();
    if (wid == 0) {
        int s = wsum[lane];
        #pragma unroll
        for (int off = 1; off < 32; off <<= 1) {
            int a = __shfl_up_sync(FULLM, s, off);
            if (lane >= off) s += a;
        }
        wsum[lane] = s;
    }
    __syncthreads();
    int base = (wid > 0) ? wsum[wid - 1] : 0;
    int incl = p + base;
    if (i < NN) g_indptr[i] = incl - v;      // exclusive within block
    if (t == 1023) g_bsum[blockIdx.x] = incl;
}

// ---------------- scan phase 2: block offsets (1 block) --------------------
__global__ void scan2_kernel() {
    __shared__ int sh[128];
    int t = threadIdx.x;
    int v = (t < NBLK) ? g_bsum[t] : 0;
    sh[t] = v;
    __syncthreads();
    #pragma unroll
    for (int off = 1; off < 128; off <<= 1) {
        int a = (t >= off) ? sh[t - off] : 0;
        __syncthreads();
        sh[t] += a;
        __syncthreads();
    }
    if (t < NBLK) g_boff[t] = sh[t] - v;     // exclusive
    if (t == NBLK - 1) g_indptr[NN] = EE - (sh[t] - v);
}

// ---------------- CSR scatter: reads ei (L2-hot) + rank, boff inline -------
__global__ void scatter_kernel(const long long* __restrict__ ei) {
    int e = (blockIdx.x * blockDim.x + threadIdx.x) * 2;
    if (e >= EE) return;
    int s0, s1, d0, d1;
    if (g_is64) {
        longlong2 sv = *(const longlong2*)&ei[e];
        longlong2 dv = *(const longlong2*)&ei[e + EE];
        s0 = (int)sv.x; s1 = (int)sv.y; d0 = (int)dv.x; d1 = (int)dv.y;
    } else {
        const int* p = (const int*)ei;
        int2 sv = *(const int2*)&p[e];
        int2 dv = *(const int2*)&p[e + EE];
        s0 = sv.x; s1 = sv.y; d0 = dv.x; d1 = dv.y;
    }
    int2 r = *(const int2*)&g_rank[e];
    g_indices[g_indptr[d0] + g_boff[d0 >> 10] + r.x] = s0;
    g_indices[g_indptr[d1] + g_boff[d1 >> 10] + r.y] = s1;
}

// ---------------- GEMM1 via HMMA (fp16 in, fp32 accum) + fused als1/ald1 ---
// 128 nodes x 64 cols per block, 8 warps. Warp wid owns rows [wid*16, wid*16+16).
// K=128 in 8 k16 steps; 8 n-tiles of 8 cols.
__global__ __launch_bounds__(256)
void gemm1_kernel(const float* __restrict__ x, const float* __restrict__ W,
                  const float* __restrict__ a_src, const float* __restrict__ a_dst) {
    extern __shared__ __half hsm[];
    __half* xa = hsm;                        // [128][XA_STRIDE]
    __half* wb = hsm + 128 * XA_STRIDE;      // [128][WB_STRIDE]
    int t = threadIdx.x;
    int bn = blockIdx.x * 128;
    // stage W (128x64 fp32 -> fp16)
    for (int i = t; i < DIN * HD / 4; i += 256) {
        float4 v = ((const float4*)W)[i];
        int r = (i * 4) >> 6, c = (i * 4) & 63;
        __half2 h0 = __floats2half2_rn(v.x, v.y);
        __half2 h1 = __floats2half2_rn(v.z, v.w);
        *(uint2*)&wb[r * WB_STRIDE + c] = make_uint2(*(unsigned*)&h0, *(unsigned*)&h1);
    }
    // stage x tile (128x128 fp32 -> fp16, zero-pad OOB rows)
    for (int i = t; i < 128 * DIN / 4; i += 256) {
        int r = (i * 4) >> 7, c = (i * 4) & 127;
        int node = bn + r;
        float4 v = (node < NN) ? *(const float4*)&x[(size_t)node * DIN + c]
                               : make_float4(0.f, 0.f, 0.f, 0.f);
        __half2 h0 = __floats2half2_rn(v.x, v.y);
        __half2 h1 = __floats2half2_rn(v.z, v.w);
        *(uint2*)&xa[r * XA_STRIDE + c] = make_uint2(*(unsigned*)&h0, *(unsigned*)&h1);
    }
    __syncthreads();

    int wid = t >> 5, lane = t & 31;
    unsigned xa_base = (unsigned)__cvta_generic_to_shared(xa);
    unsigned wb_base = (unsigned)__cvta_generic_to_shared(wb);
    float c[8][4];
    #pragma unroll
    for (int nt = 0; nt < 8; nt++)
        c[nt][0] = c[nt][1] = c[nt][2] = c[nt][3] = 0.f;

    int mrow = (lane & 7) + ((lane >> 3) & 1) * 8;   // A row within m16
    int mcol = (lane >> 4) * 8;                      // A col within k16
    int brow = (lane & 7) + ((lane >> 3) & 1) * 8;   // B k-row within k16 (lanes 0-15 used)
    #pragma unroll
    for (int ks = 0; ks < 8; ks++) {
        unsigned a0, a1, a2, a3;
        unsigned a_addr = xa_base +
            ((unsigned)((wid * 16 + mrow) * XA_STRIDE + ks * 16 + mcol) << 1);
        ldsm_x4(a0, a1, a2, a3, a_addr);
        unsigned b_row_addr = wb_base +
            ((unsigned)((ks * 16 + brow) * WB_STRIDE) << 1);
        #pragma unroll
        for (int nt = 0; nt < 8; nt++) {
            unsigned b0, b1;
            ldsm_x2t(b0, b1, b_row_addr + (unsigned)(nt * 16));
            mma16816(c[nt], a0, a1, a2, a3, b0, b1);
        }
    }

    // epilogue: C frag m16n8: lane -> rows (lane>>2), (lane>>2)+8; cols (lane&3)*2 +{0,1}
    int q = lane & 3;
    int r0 = wid * 16 + (lane >> 2);
    int node0 = bn + r0, node1 = node0 + 8;
    bool ok0 = node0 < NN, ok1 = node1 < NN;
    // fp16 h1 stores
    #pragma unroll
    for (int nt = 0; nt < 8; nt++) {
        int col = nt * 8 + q * 2;
        if (ok0) {
            __half2 p = __floats2half2_rn(c[nt][0], c[nt][1]);
            *(__half2*)&g_h1h[(size_t)node0 * HD + col] = p;
        }
        if (ok1) {
            __half2 p = __floats2half2_rn(c[nt][2], c[nt][3]);
            *(__half2*)&g_h1h[(size_t)node1 * HD + col] = p;
        }
    }
    // fused als/ald (fp32 exact dots on the fp32 accumulators)
    float ps0[4], pd0[4], ps1[4], pd1[4];
    #pragma unroll
    for (int h = 0; h < 4; h++) {
        int i0 = h * 16 + q * 2;
        int i2 = h * 16 + 8 + q * 2;
        float2 sa = *(const float2*)&a_src[i0];
        float2 sb = *(const float2*)&a_src[i2];
        float2 da = *(const float2*)&a_dst[i0];
        float2 db = *(const float2*)&a_dst[i2];
        int n0 = 2 * h, n1 = 2 * h + 1;
        ps0[h] = c[n0][0]*sa.x + c[n0][1]*sa.y + c[n1][0]*sb.x + c[n1][1]*sb.y;
        pd0[h] = c[n0][0]*da.x + c[n0][1]*da.y + c[n1][0]*db.x + c[n1][1]*db.y;
        ps1[h] = c[n0][2]*sa.x + c[n0][3]*sa.y + c[n1][2]*sb.x + c[n1][3]*sb.y;
        pd1[h] = c[n0][2]*da.x + c[n0][3]*da.y + c[n1][2]*db.x + c[n1][3]*db.y;
    }
    #pragma unroll
    for (int off = 1; off < 4; off <<= 1) {
        #pragma unroll
        for (int h = 0; h < 4; h++) {
            ps0[h] += __shfl_xor_sync(FULLM, ps0[h], off);
            pd0[h] += __shfl_xor_sync(FULLM, pd0[h], off);
            ps1[h] += __shfl_xor_sync(FULLM, ps1[h], off);
            pd1[h] += __shfl_xor_sync(FULLM, pd1[h], off);
        }
    }
    if (q == 0) {
        if (ok0) {
            *(float4*)&g_als1[node0 * 4] = make_float4(ps0[0], ps0[1], ps0[2], ps0[3]);
            *(float4*)&g_ald1[node0 * 4] = make_float4(pd0[0], pd0[1], pd0[2], pd0[3]);
        }
        if (ok1) {
            *(float4*)&g_als1[node1 * 4] = make_float4(ps1[0], ps1[1], ps1[2], ps1[3]);
            *(float4*)&g_ald1[node1 * 4] = make_float4(pd1[0], pd1[1], pd1[2], pd1[3]);
        }
    }
}

// ---------------- FUSED gather1: 4 nodes/warp (8-lane quarter per node) ----
__global__ void gather1_fused_kernel(const float* __restrict__ b1,
                                     const float* __restrict__ W2,
                                     const float* __restrict__ a_src2,
                                     const float* __restrict__ a_dst2) {
    int w = (blockIdx.x * blockDim.x + threadIdx.x) >> 5;
    if (w * 4 >= NN) return;
    int lane = threadIdx.x & 31;
    int q = lane >> 3, m = lane & 7;
    int n = 4 * w + q;                       // NN % 4 == 0 -> always valid
    int myh = m >> 1;
    float ad = g_ald1[n * 4 + myh];
    float ax[8];
    #pragma unroll
    for (int i = 0; i < 8; i++) ax[i] = 0.f;
    float z = 0.f;
    {   // self loop
        float w0 = lrelu_exp(g_als1[n * 4 + myh] + ad);
        z += w0;
        uint4 u = *(const uint4*)&g_h1h[(size_t)n * HD + m * 8];
        float2 p0 = __half22float2(*(__half2*)&u.x);
        float2 p1 = __half22float2(*(__half2*)&u.y);
        float2 p2 = __half22float2(*(__half2*)&u.z);
        float2 p3 = __half22float2(*(__half2*)&u.w);
        ax[0] += p0.x*w0; ax[1] += p0.y*w0; ax[2] += p1.x*w0; ax[3] += p1.y*w0;
        ax[4] += p2.x*w0; ax[5] += p2.y*w0; ax[6] += p3.x*w0; ax[7] += p3.y*w0;
    }
    int e   = g_indptr[n]     + g_boff[n >> 10];
    int end = g_indptr[n + 1] + g_boff[(n + 1) >> 10];
    for (; e + 4 <= end; e += 4) {
        int s0 = g_indices[e],     s1 = g_indices[e + 1];
        int s2 = g_indices[e + 2], s3 = g_indices[e + 3];
        float l0 = g_als1[s0 * 4 + myh], l1 = g_als1[s1 * 4 + myh];
        float l2 = g_als1[s2 * 4 + myh], l3 = g_als1[s3 * 4 + myh];
        uint4 u0 = *(const uint4*)&g_h1h[(size_t)s0 * HD + m * 8];
        uint4 u1 = *(const uint4*)&g_h1h[(size_t)s1 * HD + m * 8];
        uint4 u2 = *(const uint4*)&g_h1h[(size_t)s2 * HD + m * 8];
        uint4 u3 = *(const uint4*)&g_h1h[(size_t)s3 * HD + m * 8];
        float w0 = lrelu_exp(l0 + ad), w1 = lrelu_exp(l1 + ad);
        float w2 = lrelu_exp(l2 + ad), w3 = lrelu_exp(l3 + ad);
        z += (w0 + w1) + (w2 + w3);
        float2 q0 = __half22float2(*(__half2*)&u0.x), q1 = __half22float2(*(__half2*)&u0.y);
        float2 q2 = __half22float2(*(__half2*)&u0.z), q3 = __half22float2(*(__half2*)&u0.w);
        float2 r0 = __half22float2(*(__half2*)&u1.x), r1 = __half22float2(*(__half2*)&u1.y);
        float2 r2 = __half22float2(*(__half2*)&u1.z), r3 = __half22float2(*(__half2*)&u1.w);
        float2 t0 = __half22float2(*(__half2*)&u2.x), t1 = __half22float2(*(__half2*)&u2.y);
        float2 t2 = __half22float2(*(__half2*)&u2.z), t3 = __half22float2(*(__half2*)&u2.w);
        float2 v0 = __half22float2(*(__half2*)&u3.x), v1 = __half22float2(*(__half2*)&u3.y);
        float2 v2 = __half22float2(*(__half2*)&u3.z), v3 = __half22float2(*(__half2*)&u3.w);
        ax[0] += q0.x*w0 + r0.x*w1 + t0.x*w2 + v0.x*w3;
        ax[1] += q0.y*w0 + r0.y*w1 + t0.y*w2 + v0.y*w3;
        ax[2] += q1.x*w0 + r1.x*w1 + t1.x*w2 + v1.x*w3;
        ax[3] += q1.y*w0 + r1.y*w1 + t1.y*w2 + v1.y*w3;
        ax[4] += q2.x*w0 + r2.x*w1 + t2.x*w2 + v2.x*w3;
        ax[5] += q2.y*w0 + r2.y*w1 + t2.y*w2 + v2.y*w3;
        ax[6] += q3.x*w0 + r3.x*w1 + t3.x*w2 + v3.x*w3;
        ax[7] += q3.y*w0 + r3.y*w1 + t3.y*w2 + v3.y*w3;
    }
    for (; e < end; e++) {
        int s = g_indices[e];
        float l = g_als1[s * 4 + myh];
        uint4 u = *(const uint4*)&g_h1h[(size_t)s * HD + m * 8];
        float w0 = lrelu_exp(l + ad);
        z += w0;
        float2 p0 = __half22float2(*(__half2*)&u.x);
        float2 p1 = __half22float2(*(__half2*)&u.y);
        float2 p2 = __half22float2(*(__half2*)&u.z);
        float2 p3 = __half22float2(*(__half2*)&u.w);
        ax[0] += p0.x*w0; ax[1] += p0.y*w0; ax[2] += p1.x*w0; ax[3] += p1.y*w0;
        ax[4] += p2.x*w0; ax[5] += p2.y*w0; ax[6] += p3.x*w0; ax[7] += p3.y*w0;
    }
    __syncwarp();                            // re-converge before shfl epilogue
    float zi = 1.f / (z + 1e-16f);
    float4 bb0 = *(const float4*)&b1[m * 8];
    float4 bb1 = *(const float4*)&b1[m * 8 + 4];
    float f[8];
    f[0] = ax[0]*zi + bb0.x; f[1] = ax[1]*zi + bb0.y;
    f[2] = ax[2]*zi + bb0.z; f[3] = ax[3]*zi + bb0.w;
    f[4] = ax[4]*zi + bb1.x; f[5] = ax[5]*zi + bb1.y;
    f[6] = ax[6]*zi + bb1.z; f[7] = ax[7]*zi + bb1.w;
    #pragma unroll
    for (int i = 0; i < 8; i++) f[i] = f[i] > 0.f ? f[i] : expm1f(f[i]);  // ELU
    // ---- fused GEMV: lane computes output channels m*4..m*4+3 -------------
    float t0 = 0.f, t1 = 0.f, t2 = 0.f, t3 = 0.f;
    int qb = lane & 24;   // quarter base for shfl source
    #pragma unroll
    for (int k = 0; k < 8; k++) {
        #pragma unroll
        for (int j = 0; j < 8; j++) {
            float g = __shfl_sync(FULLM, f[j], qb + k);   // feat channel 8k+j of my node
            float4 wv = __ldg(&((const float4*)W2)[(8 * k + j) * 8 + m]);
            t0 += g * wv.x; t1 += g * wv.y; t2 += g * wv.z; t3 += g * wv.w;
        }
    }
    __half2 tp0 = __floats2half2_rn(t0, t1);
    __half2 tp1 = __floats2half2_rn(t2, t3);
    *(uint2*)&g_t2h[(size_t)n * DOUT + m * 4] = make_uint2(*(unsigned*)&tp0, *(unsigned*)&tp1);
    // ---- fused als2/ald2 (fp32 exact), reduce within quarter --------------
    float4 s2 = __ldg(&((const float4*)a_src2)[m]);
    float4 d2 = __ldg(&((const float4*)a_dst2)[m]);
    float ps = t0*s2.x + t1*s2.y + t2*s2.z + t3*s2.w;
    float pd = t0*d2.x + t1*d2.y + t2*d2.z + t3*d2.w;
    #pragma unroll
    for (int off = 1; off < 8; off <<= 1) {
        ps += __shfl_xor_sync(FULLM, ps, off);
        pd += __shfl_xor_sync(FULLM, pd, off);
    }
    if (m == 0) { g_als2[n] = ps; g_ald2[n] = pd; }
}

// ---------------- gather2: 8 nodes/warp (4-lane group per node) ------------
__global__ void gather2_kernel(float* __restrict__ out, const float* __restrict__ b2) {
    int w = (blockIdx.x * blockDim.x + threadIdx.x) >> 5;
    if (w * 8 >= NN) return;
    int lane = threadIdx.x & 31;
    int g = lane >> 2, ml = lane & 3;
    int n = 8 * w + g;                       // NN % 8 == 0 -> always valid
    float ad = g_ald2[n];
    float a0 = 0.f, a1 = 0.f, a2 = 0.f, a3 = 0.f;
    float a4 = 0.f, a5 = 0.f, a6 = 0.f, a7 = 0.f, z = 0.f;
    {   // self loop
        float w0 = lrelu_exp(g_als2[n] + ad);
        z += w0;
        uint4 u = *(const uint4*)&g_t2h[(size_t)n * DOUT + ml * 8];
        float2 p0 = __half22float2(*(__half2*)&u.x);
        float2 p1 = __half22float2(*(__half2*)&u.y);
        float2 p2 = __half22float2(*(__half2*)&u.z);
        float2 p3 = __half22float2(*(__half2*)&u.w);
        a0 += p0.x*w0; a1 += p0.y*w0; a2 += p1.x*w0; a3 += p1.y*w0;
        a4 += p2.x*w0; a5 += p2.y*w0; a6 += p3.x*w0; a7 += p3.y*w0;
    }
    int e   = g_indptr[n]     + g_boff[n >> 10];
    int end = g_indptr[n + 1] + g_boff[(n + 1) >> 10];
    for (; e + 4 <= end; e += 4) {
        int s0 = g_indices[e],     s1 = g_indices[e + 1];
        int s2 = g_indices[e + 2], s3 = g_indices[e + 3];
        float l0 = g_als2[s0], l1 = g_als2[s1], l2 = g_als2[s2], l3 = g_als2[s3];
        uint4 u0 = *(const uint4*)&g_t2h[(size_t)s0 * DOUT + ml * 8];
        uint4 u1 = *(const uint4*)&g_t2h[(size_t)s1 * DOUT + ml * 8];
        uint4 u2 = *(const uint4*)&g_t2h[(size_t)s2 * DOUT + ml * 8];
        uint4 u3 = *(const uint4*)&g_t2h[(size_t)s3 * DOUT + ml * 8];
        float w0 = lrelu_exp(l0 + ad), w1 = lrelu_exp(l1 + ad);
        float w2 = lrelu_exp(l2 + ad), w3 = lrelu_exp(l3 + ad);
        z += (w0 + w1) + (w2 + w3);
        float2 q0 = __half22float2(*(__half2*)&u0.x), q1 = __half22float2(*(__half2*)&u0.y);
        float2 q2 = __half22float2(*(__half2*)&u0.z), q3 = __half22float2(*(__half2*)&u0.w);
        float2 r0 = __half22float2(*(__half2*)&u1.x), r1 = __half22float2(*(__half2*)&u1.y);
        float2 r2 = __half22float2(*(__half2*)&u1.z), r3 = __half22float2(*(__half2*)&u1.w);
        float2 t0 = __half22float2(*(__half2*)&u2.x), t1 = __half22float2(*(__half2*)&u2.y);
        float2 t2 = __half22float2(*(__half2*)&u2.z), t3 = __half22float2(*(__half2*)&u2.w);
        float2 v0 = __half22float2(*(__half2*)&u3.x), v1 = __half22float2(*(__half2*)&u3.y);
        float2 v2 = __half22float2(*(__half2*)&u3.z), v3 = __half22float2(*(__half2*)&u3.w);
        a0 += q0.x*w0 + r0.x*w1 + t0.x*w2 + v0.x*w3;
        a1 += q0.y*w0 + r0.y*w1 + t0.y*w2 + v0.y*w3;
        a2 += q1.x*w0 + r1.x*w1 + t1.x*w2 + v1.x*w3;
        a3 += q1.y*w0 + r1.y*w1 + t1.y*w2 + v1.y*w3;
        a4 += q2.x*w0 + r2.x*w1 + t2.x*w2 + v2.x*w3;
        a5 += q2.y*w0 + r2.y*w1 + t2.y*w2 + v2.y*w3;
        a6 += q3.x*w0 + r3.x*w1 + t3.x*w2 + v3.x*w3;
        a7 += q3.y*w0 + r3.y*w1 + t3.y*w2 + v3.y*w3;
    }
    for (; e < end; e++) {
        int s = g_indices[e];
        float l = g_als2[s];
        uint4 u = *(const uint4*)&g_t2h[(size_t)s * DOUT + ml * 8];
        float w0 = lrelu_exp(l + ad);
        z += w0;
        float2 p0 = __half22float2(*(__half2*)&u.x);
        float2 p1 = __half22float2(*(__half2*)&u.y);
        float2 p2 = __half22float2(*(__half2*)&u.z);
        float2 p3 = __half22float2(*(__half2*)&u.w);
        a0 += p0.x*w0; a1 += p0.y*w0; a2 += p1.x*w0; a3 += p1.y*w0;
        a4 += p2.x*w0; a5 += p2.y*w0; a6 += p3.x*w0; a7 += p3.y*w0;
    }
    float zi = 1.f / (z + 1e-16f);
    float4 bb0 = *(const float4*)&b2[ml * 8];
    float4 bb1 = *(const float4*)&b2[ml * 8 + 4];
    float* op = &out[(size_t)n * DOUT + ml * 8];
    *(float4*)op       = make_float4(a0 * zi + bb0.x, a1 * zi + bb0.y,
                                     a2 * zi + bb0.z, a3 * zi + bb0.w);
    *(float4*)(op + 4) = make_float4(a4 * zi + bb1.x, a5 * zi + bb1.y,
                                     a6 * zi + bb1.z, a7 * zi + bb1.w);
}

// ---------------------------------------------------------------------------
extern "C" void kernel_launch(void* const* d_in, const int* in_sizes, int n_in,
                              void* d_out, int out_size) {
    const float*     x      = (const float*)d_in[0];
    const long long* ei     = (const long long*)d_in[1];
    const float*     W1     = (const float*)d_in[2];
    const float*     a_src1 = (const float*)d_in[3];
    const float*     a_dst1 = (const float*)d_in[4];
    const float*     b1     = (const float*)d_in[5];
    const float*     W2     = (const float*)d_in[6];
    const float*     a_src2 = (const float*)d_in[7];
    const float*     a_dst2 = (const float*)d_in[8];
    const float*     b2     = (const float*)d_in[9];
    float* out = (float*)d_out;

    const int GB  = (NN + 127) / 128;
    const int E2  = (EE / 2 + 255) / 256;
    const int WB1 = ((NN / 4) * 32 + 255) / 256;   // 4 nodes per warp
    const int WB2 = ((NN / 8) * 32 + 255) / 256;   // 8 nodes per warp

    // zero degree counters via memset node (not a kernel launch)
    void* cntPtr = nullptr;
    cudaGetSymbolAddress(&cntPtr, g_cnt);
    cudaMemsetAsync(cntPtr, 0, NN * sizeof(int), 0);

    cudaEventRecord(g_evFork, 0);
    cudaStreamWaitEvent(g_s2, g_evFork, 0);

    detect_kernel<<<1, 32>>>(ei);
    convert_count_kernel<<<E2, 256>>>(ei);
    scan1_kernel<<<NBLK, 1024>>>();
    gemm1_kernel<<<GB, 256, G1_SMEM, g_s2>>>(x, W1, a_src1, a_dst1);
    cudaEventRecord(g_evJoin, g_s2);
    scan2_kernel<<<1, 128>>>();
    scatter_kernel<<<E2, 256>>>(ei);

    cudaStreamWaitEvent(0, g_evJoin, 0);
    gather1_fused_kernel<<<WB1, 256>>>(b1, W2, a_src2, a_dst2);
    gather2_kernel<<<WB2, 256>>>(out, b2);
}